// round 8
// baseline (speedup 1.0000x reference)
#include <cuda_runtime.h>
#include <cuda_bf16.h>
#include <cuda_fp16.h>
#include <cstdint>

#define D_MODEL 1024
#define NHEAD   16
#define HDIM    64
#define BATCH   4
#define SEQ     2048
#define NTOK    (BATCH*SEQ)

// Scratch (allocation-free per harness rules)
__device__ float g_q[(size_t)NTOK * D_MODEL];
__device__ float g_k[(size_t)NTOK * D_MODEL];
__device__ float g_v[(size_t)NTOK * D_MODEL];
__device__ float g_att[(size_t)NTOK * D_MODEL];

// ---------------------------------------------------------------------------
// helpers
// ---------------------------------------------------------------------------
__device__ __forceinline__ uint32_t smem_u32(const void* p) {
    uint32_t a;
    asm("{ .reg .u64 t; cvta.to.shared.u64 t, %1; cvt.u32.u64 %0, t; }"
        : "=r"(a) : "l"(p));
    return a;
}
__device__ __forceinline__ void ldm_x4(uint32_t r[4], uint32_t addr) {
    asm volatile("ldmatrix.sync.aligned.m8n8.x4.shared.b16 {%0,%1,%2,%3}, [%4];"
                 : "=r"(r[0]), "=r"(r[1]), "=r"(r[2]), "=r"(r[3]) : "r"(addr));
}
__device__ __forceinline__ void ldm_x4_t(uint32_t r[4], uint32_t addr) {
    asm volatile("ldmatrix.sync.aligned.m8n8.x4.trans.shared.b16 {%0,%1,%2,%3}, [%4];"
                 : "=r"(r[0]), "=r"(r[1]), "=r"(r[2]), "=r"(r[3]) : "r"(addr));
}
// bf16 mma (GEMMs)
__device__ __forceinline__ void mma16816(float c[4], const uint32_t a[4],
                                         uint32_t b0, uint32_t b1) {
    asm volatile(
        "mma.sync.aligned.m16n8k16.row.col.f32.bf16.bf16.f32 "
        "{%0,%1,%2,%3}, {%4,%5,%6,%7}, {%8,%9}, {%0,%1,%2,%3};"
        : "+f"(c[0]), "+f"(c[1]), "+f"(c[2]), "+f"(c[3])
        : "r"(a[0]), "r"(a[1]), "r"(a[2]), "r"(a[3]), "r"(b0), "r"(b1));
}
// fp16 mma (attention)
__device__ __forceinline__ void mma16816h(float c[4], const uint32_t a[4],
                                          uint32_t b0, uint32_t b1) {
    asm volatile(
        "mma.sync.aligned.m16n8k16.row.col.f32.f16.f16.f32 "
        "{%0,%1,%2,%3}, {%4,%5,%6,%7}, {%8,%9}, {%0,%1,%2,%3};"
        : "+f"(c[0]), "+f"(c[1]), "+f"(c[2]), "+f"(c[3])
        : "r"(a[0]), "r"(a[1]), "r"(a[2]), "r"(a[3]), "r"(b0), "r"(b1));
}
// bf16 splits (GEMMs)
__device__ __forceinline__ void split2(float f0, float f1,
                                       uint32_t& hi, uint32_t& lo) {
    __nv_bfloat162 h = __float22bfloat162_rn(make_float2(f0, f1));
    float2 hf = make_float2(__low2float(h), __high2float(h));
    __nv_bfloat162 l = __float22bfloat162_rn(make_float2(f0 - hf.x, f1 - hf.y));
    hi = *(uint32_t*)&h; lo = *(uint32_t*)&l;
}
__device__ __forceinline__ void split_f4(float4 v, uint2& hi, uint2& lo) {
    split2(v.x, v.y, hi.x, lo.x);
    split2(v.z, v.w, hi.y, lo.y);
}
// fp16 splits / pack (attention)
__device__ __forceinline__ void split2h(float f0, float f1,
                                        uint32_t& hi, uint32_t& lo) {
    __half2 h = __floats2half2_rn(f0, f1);
    float2 hf = __half22float2(h);
    __half2 l = __floats2half2_rn(f0 - hf.x, f1 - hf.y);
    hi = *(uint32_t*)&h; lo = *(uint32_t*)&l;
}
__device__ __forceinline__ void split_f4h(float4 v, uint2& hi, uint2& lo) {
    split2h(v.x, v.y, hi.x, lo.x);
    split2h(v.z, v.w, hi.y, lo.y);
}
__device__ __forceinline__ uint32_t pack2h(float f0, float f1) {
    __half2 h = __floats2half2_rn(f0, f1);
    return *(uint32_t*)&h;
}

// ---------------------------------------------------------------------------
// GEMM: C[8192,1024] = A @ W^T + bias  via bf16x3 mma.sync  (unchanged R4)
// ---------------------------------------------------------------------------
#define LDT     72
#define TILE_B  (128 * LDT * 2)
#define STAGE_B (4 * TILE_B)
#define DSMEM_B (2 * STAGE_B)

__global__ __launch_bounds__(256, 1)
void gemm_bf16x3(const float* __restrict__ A, const float* __restrict__ W,
                 const float* __restrict__ bias, float* __restrict__ C)
{
    extern __shared__ char sm[];
    const uint32_t s0 = smem_u32(sm);

    const int tid  = threadIdx.x;
    const int lane = tid & 31;
    const int wid  = tid >> 5;
    const int bm = blockIdx.y * 128;
    const int bn = blockIdx.x * 128;
    const int wm = (wid >> 2) * 64;
    const int wn = (wid & 3) * 32;

    float acc[4][4][4];
#pragma unroll
    for (int i = 0; i < 4; i++)
#pragma unroll
        for (int j = 0; j < 4; j++)
#pragma unroll
            for (int q = 0; q < 4; q++) acc[i][j][q] = 0.f;

    const uint32_t offA = (uint32_t)(lane & 15) * 144 + (uint32_t)(lane >> 4) * 16;
    const uint32_t offB = (uint32_t)((lane & 7) + ((lane >> 4) & 1) * 8) * 144
                        + (uint32_t)((lane >> 3) & 1) * 16;

    float4 av[8], bv[8];
#pragma unroll
    for (int j = 0; j < 8; j++) {
        int i = tid + j * 256;
        int row = i >> 4, c4 = i & 15;
        av[j] = *(const float4*)(A + (size_t)(bm + row) * D_MODEL + c4 * 4);
        bv[j] = *(const float4*)(W + (size_t)(bn + row) * D_MODEL + c4 * 4);
    }
    {
        char* stg = sm;
#pragma unroll
        for (int j = 0; j < 8; j++) {
            int i = tid + j * 256;
            int row = i >> 4, c4 = i & 15;
            uint32_t ad = (uint32_t)(row * 144 + c4 * 8);
            uint2 hi, lo;
            split_f4(av[j], hi, lo);
            *(uint2*)(stg + 0 * TILE_B + ad) = hi;
            *(uint2*)(stg + 1 * TILE_B + ad) = lo;
            split_f4(bv[j], hi, lo);
            *(uint2*)(stg + 2 * TILE_B + ad) = hi;
            *(uint2*)(stg + 3 * TILE_B + ad) = lo;
        }
    }
    __syncthreads();

    for (int kt = 0; kt < 16; kt++) {
        if (kt < 15) {
#pragma unroll
            for (int j = 0; j < 8; j++) {
                int i = tid + j * 256;
                int row = i >> 4, c4 = i & 15;
                av[j] = *(const float4*)(A + (size_t)(bm + row) * D_MODEL
                                         + (kt + 1) * 64 + c4 * 4);
                bv[j] = *(const float4*)(W + (size_t)(bn + row) * D_MODEL
                                         + (kt + 1) * 64 + c4 * 4);
            }
        }

        const uint32_t sb = s0 + (uint32_t)(kt & 1) * STAGE_B;
        const uint32_t sAh = sb, sAl = sb + TILE_B;
        const uint32_t sBh = sb + 2 * TILE_B, sBl = sb + 3 * TILE_B;

#pragma unroll
        for (int ks = 0; ks < 4; ks++) {
            uint32_t ah[4][4], al[4][4], bh[2][4], bl[2][4];
            const uint32_t ka = (uint32_t)ks * 32;
#pragma unroll
            for (int mt = 0; mt < 4; mt++) {
                uint32_t ra = (uint32_t)((wm + mt * 16) * 144) + offA + ka;
                ldm_x4(ah[mt], sAh + ra);
                ldm_x4(al[mt], sAl + ra);
            }
#pragma unroll
            for (int p = 0; p < 2; p++) {
                uint32_t rb = (uint32_t)((wn + p * 16) * 144) + offB + ka;
                ldm_x4(bh[p], sBh + rb);
                ldm_x4(bl[p], sBl + rb);
            }
#pragma unroll
            for (int mt = 0; mt < 4; mt++)
#pragma unroll
                for (int nt = 0; nt < 4; nt++) {
                    uint32_t h0 = bh[nt >> 1][(nt & 1) * 2];
                    uint32_t h1 = bh[nt >> 1][(nt & 1) * 2 + 1];
                    uint32_t l0 = bl[nt >> 1][(nt & 1) * 2];
                    uint32_t l1 = bl[nt >> 1][(nt & 1) * 2 + 1];
                    mma16816(acc[mt][nt], ah[mt], h0, h1);
                    mma16816(acc[mt][nt], ah[mt], l0, l1);
                    mma16816(acc[mt][nt], al[mt], h0, h1);
                }
        }

        if (kt < 15) {
            char* stg = sm + ((kt + 1) & 1) * STAGE_B;
#pragma unroll
            for (int j = 0; j < 8; j++) {
                int i = tid + j * 256;
                int row = i >> 4, c4 = i & 15;
                uint32_t ad = (uint32_t)(row * 144 + c4 * 8);
                uint2 hi, lo;
                split_f4(av[j], hi, lo);
                *(uint2*)(stg + 0 * TILE_B + ad) = hi;
                *(uint2*)(stg + 1 * TILE_B + ad) = lo;
                split_f4(bv[j], hi, lo);
                *(uint2*)(stg + 2 * TILE_B + ad) = hi;
                *(uint2*)(stg + 3 * TILE_B + ad) = lo;
            }
        }
        __syncthreads();
    }

#pragma unroll
    for (int mt = 0; mt < 4; mt++) {
        int row0 = bm + wm + mt * 16 + (lane >> 2);
#pragma unroll
        for (int nt = 0; nt < 4; nt++) {
            int col = bn + wn + nt * 8 + (lane & 3) * 2;
            float2 b2 = *(const float2*)&bias[col];
            float2 o0 = make_float2(acc[mt][nt][0] + b2.x, acc[mt][nt][1] + b2.y);
            float2 o1 = make_float2(acc[mt][nt][2] + b2.x, acc[mt][nt][3] + b2.y);
            *(float2*)(C + (size_t)row0 * D_MODEL + col) = o0;
            *(float2*)(C + (size_t)(row0 + 8) * D_MODEL + col) = o1;
        }
    }
}

// ---------------------------------------------------------------------------
// Flash attention — R4 structure (128 thr, 4 warps x 32 q-rows, BN=64),
// now fp16: QK = 3-pass fp16 split; PV = 2-pass (P single fp16, V hi/lo).
// smem: Qhi/Qlo [128][72]fp16 resident, Khi/Klo/Vhi/Vlo [64][72] per tile.
// ---------------------------------------------------------------------------
#define AQH 0
#define AQL 18432
#define AKH 36864
#define AKL 46080
#define AVH 55296
#define AVL 64512
#define A_SMEM 73728

__global__ __launch_bounds__(128)
void attn_mma(const float* __restrict__ Qg, const float* __restrict__ Kg,
              const float* __restrict__ Vg, float* __restrict__ Og)
{
    extern __shared__ char sm[];
    const uint32_t s0 = smem_u32(sm);

    const int tid  = threadIdx.x;
    const int lane = tid & 31;
    const int wid  = tid >> 5;
    const int qt = blockIdx.x;          // 16 q-tiles
    const int bh = blockIdx.y;          // 64 (b,h)
    const int b = bh >> 4, h = bh & 15;

    const size_t tok0 = (size_t)b * SEQ + qt * 128;
    const float* Qb = Qg + tok0 * D_MODEL + h * 64;
    const float* Kb = Kg + (size_t)b * SEQ * D_MODEL + h * 64;
    const float* Vb = Vg + (size_t)b * SEQ * D_MODEL + h * 64;

    const uint32_t laneA = (uint32_t)(((lane >> 3) & 1) * 8 + (lane & 7)) * 144
                         + (uint32_t)(lane >> 4) * 16;   // A frags (Q) and V trans
    const uint32_t laneB = (uint32_t)((lane >> 4) * 8 + (lane & 7)) * 144
                         + (uint32_t)((lane >> 3) & 1) * 16;  // B frags (K)
    const uint32_t wq = (uint32_t)wid * 32 * 144;

    // load Q tile (128 x 64 fp32), split into fp16 Qhi/Qlo
    for (int i = tid; i < 128 * 16; i += 128) {
        int row = i >> 4, c4 = i & 15;
        float4 v = *(const float4*)(Qb + (size_t)row * D_MODEL + c4 * 4);
        uint2 hi, lo;
        split_f4h(v, hi, lo);
        uint32_t ad = (uint32_t)(row * 144 + c4 * 8);
        *(uint2*)(sm + AQH + ad) = hi;
        *(uint2*)(sm + AQL + ad) = lo;
    }

    float o[2][8][4];
#pragma unroll
    for (int mt = 0; mt < 2; mt++)
#pragma unroll
        for (int dn = 0; dn < 8; dn++)
#pragma unroll
            for (int q = 0; q < 4; q++) o[mt][dn][q] = 0.f;
    float mrow[4] = {-1e30f, -1e30f, -1e30f, -1e30f};
    float lrow[4] = {0.f, 0.f, 0.f, 0.f};

    const float SC = 0.125f;  // 1/sqrt(64)

    for (int kt = 0; kt < SEQ / 64; kt++) {
        __syncthreads();   // previous tile's smem reads complete
        // load K,V tiles (64 x 64 fp32 each), split to fp16 hi/lo
        for (int i = tid; i < 64 * 16; i += 128) {
            int row = i >> 4, c4 = i & 15;
            size_t gro = (size_t)(kt * 64 + row) * D_MODEL + c4 * 4;
            uint32_t ad = (uint32_t)(row * 144 + c4 * 8);
            uint2 hi, lo;
            split_f4h(*(const float4*)(Kb + gro), hi, lo);
            *(uint2*)(sm + AKH + ad) = hi;
            *(uint2*)(sm + AKL + ad) = lo;
            split_f4h(*(const float4*)(Vb + gro), hi, lo);
            *(uint2*)(sm + AVH + ad) = hi;
            *(uint2*)(sm + AVL + ad) = lo;
        }
        __syncthreads();

        // ---- S = Q @ K^T (3-pass fp16 split)
        float s[2][8][4];
#pragma unroll
        for (int mt = 0; mt < 2; mt++)
#pragma unroll
            for (int nt = 0; nt < 8; nt++)
#pragma unroll
                for (int q = 0; q < 4; q++) s[mt][nt][q] = 0.f;

#pragma unroll
        for (int k = 0; k < 4; k++) {
            uint32_t bhf[4][4], blf[4][4];
#pragma unroll
            for (int np = 0; np < 4; np++) {
                uint32_t rb = (uint32_t)(np * 16 * 144) + k * 32 + laneB;
                ldm_x4(bhf[np], s0 + AKH + rb);
                ldm_x4(blf[np], s0 + AKL + rb);
            }
#pragma unroll
            for (int mt = 0; mt < 2; mt++) {
                uint32_t ah[4], al[4];
                uint32_t ra = wq + (uint32_t)(mt * 16 * 144) + k * 32 + laneA;
                ldm_x4(ah, s0 + AQH + ra);
                ldm_x4(al, s0 + AQL + ra);
#pragma unroll
                for (int nt = 0; nt < 8; nt++) {
                    uint32_t h0 = bhf[nt >> 1][(nt & 1) * 2];
                    uint32_t h1 = bhf[nt >> 1][(nt & 1) * 2 + 1];
                    uint32_t l0 = blf[nt >> 1][(nt & 1) * 2];
                    uint32_t l1 = blf[nt >> 1][(nt & 1) * 2 + 1];
                    mma16816h(s[mt][nt], ah, h0, h1);
                    mma16816h(s[mt][nt], ah, l0, l1);
                    mma16816h(s[mt][nt], al, h0, h1);
                }
            }
        }

        // ---- online softmax in fragments (rows rr = mt*2 + hilo)
        float corr[4];
#pragma unroll
        for (int rr = 0; rr < 4; rr++) {
            int mt = rr >> 1, c0 = (rr & 1) * 2;
            float mx = -1e30f;
#pragma unroll
            for (int nt = 0; nt < 8; nt++)
                mx = fmaxf(mx, fmaxf(s[mt][nt][c0], s[mt][nt][c0 + 1]));
            mx = fmaxf(mx, __shfl_xor_sync(0xffffffffu, mx, 1));
            mx = fmaxf(mx, __shfl_xor_sync(0xffffffffu, mx, 2));
            float mn = fmaxf(mrow[rr], mx);
            corr[rr] = __expf((mrow[rr] - mn) * SC);
            mrow[rr] = mn;
            float rs = 0.f;
#pragma unroll
            for (int nt = 0; nt < 8; nt++) {
                float e0 = __expf((s[mt][nt][c0] - mn) * SC);
                float e1 = __expf((s[mt][nt][c0 + 1] - mn) * SC);
                s[mt][nt][c0] = e0; s[mt][nt][c0 + 1] = e1;
                rs += e0 + e1;
            }
            rs += __shfl_xor_sync(0xffffffffu, rs, 1);
            rs += __shfl_xor_sync(0xffffffffu, rs, 2);
            lrow[rr] = lrow[rr] * corr[rr] + rs;
        }
#pragma unroll
        for (int mt = 0; mt < 2; mt++)
#pragma unroll
            for (int dn = 0; dn < 8; dn++) {
                o[mt][dn][0] *= corr[mt * 2];
                o[mt][dn][1] *= corr[mt * 2];
                o[mt][dn][2] *= corr[mt * 2 + 1];
                o[mt][dn][3] *= corr[mt * 2 + 1];
            }

        // ---- O += P @ V (2-pass: P single fp16, V hi + V lo)
#pragma unroll
        for (int kk = 0; kk < 4; kk++) {
            uint32_t vhf[4][4], vlf[4][4];
#pragma unroll
            for (int dp = 0; dp < 4; dp++) {
                uint32_t rv = (uint32_t)(kk * 16 * 144) + dp * 32 + laneA;
                ldm_x4_t(vhf[dp], s0 + AVH + rv);
                ldm_x4_t(vlf[dp], s0 + AVL + rv);
            }
#pragma unroll
            for (int mt = 0; mt < 2; mt++) {
                uint32_t ph[4];
                ph[0] = pack2h(s[mt][2 * kk][0],     s[mt][2 * kk][1]);
                ph[1] = pack2h(s[mt][2 * kk][2],     s[mt][2 * kk][3]);
                ph[2] = pack2h(s[mt][2 * kk + 1][0], s[mt][2 * kk + 1][1]);
                ph[3] = pack2h(s[mt][2 * kk + 1][2], s[mt][2 * kk + 1][3]);
#pragma unroll
                for (int dn = 0; dn < 8; dn++) {
                    uint32_t h0 = vhf[dn >> 1][(dn & 1) * 2];
                    uint32_t h1 = vhf[dn >> 1][(dn & 1) * 2 + 1];
                    uint32_t l0 = vlf[dn >> 1][(dn & 1) * 2];
                    uint32_t l1 = vlf[dn >> 1][(dn & 1) * 2 + 1];
                    mma16816h(o[mt][dn], ph, h0, h1);
                    mma16816h(o[mt][dn], ph, l0, l1);
                }
            }
        }
    }

    // ---- epilogue
    float inv[4];
#pragma unroll
    for (int rr = 0; rr < 4; rr++) inv[rr] = 1.f / lrow[rr];
#pragma unroll
    for (int mt = 0; mt < 2; mt++) {
        size_t row0 = tok0 + wid * 32 + mt * 16 + (lane >> 2);
#pragma unroll
        for (int dn = 0; dn < 8; dn++) {
            int col = h * 64 + dn * 8 + (lane & 3) * 2;
            float2 o0 = make_float2(o[mt][dn][0] * inv[mt * 2],
                                    o[mt][dn][1] * inv[mt * 2]);
            float2 o1 = make_float2(o[mt][dn][2] * inv[mt * 2 + 1],
                                    o[mt][dn][3] * inv[mt * 2 + 1]);
            *(float2*)(Og + row0 * D_MODEL + col) = o0;
            *(float2*)(Og + (row0 + 8) * D_MODEL + col) = o1;
        }
    }
}

// ---------------------------------------------------------------------------
extern "C" void kernel_launch(void* const* d_in, const int* in_sizes, int n_in,
                              void* d_out, int out_size)
{
    const float* q  = (const float*)d_in[0];
    const float* k  = (const float*)d_in[1];
    const float* v  = (const float*)d_in[2];
    const float* Wq = (const float*)d_in[3];
    const float* bq = (const float*)d_in[4];
    const float* Wk = (const float*)d_in[5];
    const float* bk = (const float*)d_in[6];
    const float* Wv = (const float*)d_in[7];
    const float* bv = (const float*)d_in[8];
    const float* Wo = (const float*)d_in[9];
    const float* bo = (const float*)d_in[10];
    float* out = (float*)d_out;

    float *gq, *gk, *gv, *ga;
    cudaGetSymbolAddress((void**)&gq, g_q);
    cudaGetSymbolAddress((void**)&gk, g_k);
    cudaGetSymbolAddress((void**)&gv, g_v);
    cudaGetSymbolAddress((void**)&ga, g_att);

    cudaFuncSetAttribute(gemm_bf16x3,
                         cudaFuncAttributeMaxDynamicSharedMemorySize, DSMEM_B);
    cudaFuncSetAttribute(attn_mma,
                         cudaFuncAttributeMaxDynamicSharedMemorySize, A_SMEM);

    dim3 ggrid(D_MODEL / 128, NTOK / 128);   // (8, 64)
    gemm_bf16x3<<<ggrid, 256, DSMEM_B>>>(q, Wq, bq, gq);
    gemm_bf16x3<<<ggrid, 256, DSMEM_B>>>(k, Wk, bk, gk);
    gemm_bf16x3<<<ggrid, 256, DSMEM_B>>>(v, Wv, bv, gv);

    attn_mma<<<dim3(SEQ / 128, BATCH * NHEAD), 128, A_SMEM>>>(gq, gk, gv, ga);

    gemm_bf16x3<<<ggrid, 256, DSMEM_B>>>(ga, Wo, bo, out);
}

// round 9
// speedup vs baseline: 1.0776x; 1.0776x over previous
#include <cuda_runtime.h>
#include <cuda_bf16.h>
#include <cuda_fp16.h>
#include <cstdint>

#define D_MODEL 1024
#define NHEAD   16
#define HDIM    64
#define BATCH   4
#define SEQ     2048
#define NTOK    (BATCH*SEQ)

// Scratch (allocation-free per harness rules)
__device__ float g_q[(size_t)NTOK * D_MODEL];
__device__ float g_k[(size_t)NTOK * D_MODEL];
__device__ float g_v[(size_t)NTOK * D_MODEL];
__device__ float g_att[(size_t)NTOK * D_MODEL];

// ---------------------------------------------------------------------------
// helpers
// ---------------------------------------------------------------------------
__device__ __forceinline__ uint32_t smem_u32(const void* p) {
    uint32_t a;
    asm("{ .reg .u64 t; cvta.to.shared.u64 t, %1; cvt.u32.u64 %0, t; }"
        : "=r"(a) : "l"(p));
    return a;
}
__device__ __forceinline__ void ldm_x4(uint32_t r[4], uint32_t addr) {
    asm volatile("ldmatrix.sync.aligned.m8n8.x4.shared.b16 {%0,%1,%2,%3}, [%4];"
                 : "=r"(r[0]), "=r"(r[1]), "=r"(r[2]), "=r"(r[3]) : "r"(addr));
}
__device__ __forceinline__ void ldm_x4_t(uint32_t r[4], uint32_t addr) {
    asm volatile("ldmatrix.sync.aligned.m8n8.x4.trans.shared.b16 {%0,%1,%2,%3}, [%4];"
                 : "=r"(r[0]), "=r"(r[1]), "=r"(r[2]), "=r"(r[3]) : "r"(addr));
}
// bf16 mma (attention)
__device__ __forceinline__ void mma16816(float c[4], const uint32_t a[4],
                                         uint32_t b0, uint32_t b1) {
    asm volatile(
        "mma.sync.aligned.m16n8k16.row.col.f32.bf16.bf16.f32 "
        "{%0,%1,%2,%3}, {%4,%5,%6,%7}, {%8,%9}, {%0,%1,%2,%3};"
        : "+f"(c[0]), "+f"(c[1]), "+f"(c[2]), "+f"(c[3])
        : "r"(a[0]), "r"(a[1]), "r"(a[2]), "r"(a[3]), "r"(b0), "r"(b1));
}
// fp16 mma (GEMMs)
__device__ __forceinline__ void mma16816h(float c[4], const uint32_t a[4],
                                          uint32_t b0, uint32_t b1) {
    asm volatile(
        "mma.sync.aligned.m16n8k16.row.col.f32.f16.f16.f32 "
        "{%0,%1,%2,%3}, {%4,%5,%6,%7}, {%8,%9}, {%0,%1,%2,%3};"
        : "+f"(c[0]), "+f"(c[1]), "+f"(c[2]), "+f"(c[3])
        : "r"(a[0]), "r"(a[1]), "r"(a[2]), "r"(a[3]), "r"(b0), "r"(b1));
}
// bf16 splits (attention)
__device__ __forceinline__ void split2(float f0, float f1,
                                       uint32_t& hi, uint32_t& lo) {
    __nv_bfloat162 h = __float22bfloat162_rn(make_float2(f0, f1));
    float2 hf = make_float2(__low2float(h), __high2float(h));
    __nv_bfloat162 l = __float22bfloat162_rn(make_float2(f0 - hf.x, f1 - hf.y));
    hi = *(uint32_t*)&h; lo = *(uint32_t*)&l;
}
__device__ __forceinline__ void split_f4(float4 v, uint2& hi, uint2& lo) {
    split2(v.x, v.y, hi.x, lo.x);
    split2(v.z, v.w, hi.y, lo.y);
}
// fp16 split / pack (GEMMs)
__device__ __forceinline__ void split2h(float f0, float f1,
                                        uint32_t& hi, uint32_t& lo) {
    __half2 h = __floats2half2_rn(f0, f1);
    float2 hf = __half22float2(h);
    __half2 l = __floats2half2_rn(f0 - hf.x, f1 - hf.y);
    hi = *(uint32_t*)&h; lo = *(uint32_t*)&l;
}
__device__ __forceinline__ void split_f4h(float4 v, uint2& hi, uint2& lo) {
    split2h(v.x, v.y, hi.x, lo.x);
    split2h(v.z, v.w, hi.y, lo.y);
}
__device__ __forceinline__ uint32_t pack2h(float f0, float f1) {
    __half2 h = __floats2half2_rn(f0, f1);
    return *(uint32_t*)&h;
}
__device__ __forceinline__ uint2 pack_f4h(float4 v) {
    uint2 r;
    r.x = pack2h(v.x, v.y);
    r.y = pack2h(v.z, v.w);
    return r;
}

// ---------------------------------------------------------------------------
// GEMM: C[8192,1024] = A @ W^T + bias  — fp16 2-pass:
// A quantized to single fp16 (err ~2.8e-4), W split fp16 hi/lo.
// 128x128 tile, BK=64, 256 thr, 8 warps (64x32 warp tiles), double buffer.
// grid.z selects one of up to 3 (A,W,bias,C) problem instances.
// ---------------------------------------------------------------------------
#define GT_B    18432                // one tile: 128 rows * 144B
#define GSTG_B  (3 * GT_B)           // Ah | Wh | Wl = 55296
#define GSM_B   (2 * GSTG_B)         // 110592

__global__ __launch_bounds__(256, 1)
void gemm_f16x2(const float* __restrict__ A0, const float* __restrict__ W0,
                const float* __restrict__ b0_, float* __restrict__ C0,
                const float* __restrict__ A1, const float* __restrict__ W1,
                const float* __restrict__ b1_, float* __restrict__ C1,
                const float* __restrict__ A2, const float* __restrict__ W2,
                const float* __restrict__ b2_, float* __restrict__ C2)
{
    extern __shared__ char sm[];
    const uint32_t s0 = smem_u32(sm);

    const int z = blockIdx.z;
    const float* A    = (z == 0) ? A0  : (z == 1) ? A1  : A2;
    const float* W    = (z == 0) ? W0  : (z == 1) ? W1  : W2;
    const float* bias = (z == 0) ? b0_ : (z == 1) ? b1_ : b2_;
    float*       C    = (z == 0) ? C0  : (z == 1) ? C1  : C2;

    const int tid  = threadIdx.x;
    const int lane = tid & 31;
    const int wid  = tid >> 5;
    const int bm = blockIdx.y * 128;
    const int bn = blockIdx.x * 128;
    const int wm = (wid >> 2) * 64;
    const int wn = (wid & 3) * 32;

    float acc[4][4][4];
#pragma unroll
    for (int i = 0; i < 4; i++)
#pragma unroll
        for (int j = 0; j < 4; j++)
#pragma unroll
            for (int q = 0; q < 4; q++) acc[i][j][q] = 0.f;

    const uint32_t offA = (uint32_t)(lane & 15) * 144 + (uint32_t)(lane >> 4) * 16;
    const uint32_t offB = (uint32_t)((lane & 7) + ((lane >> 4) & 1) * 8) * 144
                        + (uint32_t)((lane >> 3) & 1) * 16;

    float4 av[8], bv[8];
#pragma unroll
    for (int j = 0; j < 8; j++) {
        int i = tid + j * 256;
        int row = i >> 4, c4 = i & 15;
        av[j] = *(const float4*)(A + (size_t)(bm + row) * D_MODEL + c4 * 4);
        bv[j] = *(const float4*)(W + (size_t)(bn + row) * D_MODEL + c4 * 4);
    }
    {
        char* stg = sm;
#pragma unroll
        for (int j = 0; j < 8; j++) {
            int i = tid + j * 256;
            int row = i >> 4, c4 = i & 15;
            uint32_t ad = (uint32_t)(row * 144 + c4 * 8);
            *(uint2*)(stg + 0 * GT_B + ad) = pack_f4h(av[j]);
            uint2 hi, lo;
            split_f4h(bv[j], hi, lo);
            *(uint2*)(stg + 1 * GT_B + ad) = hi;
            *(uint2*)(stg + 2 * GT_B + ad) = lo;
        }
    }
    __syncthreads();

    for (int kt = 0; kt < 16; kt++) {
        if (kt < 15) {
#pragma unroll
            for (int j = 0; j < 8; j++) {
                int i = tid + j * 256;
                int row = i >> 4, c4 = i & 15;
                av[j] = *(const float4*)(A + (size_t)(bm + row) * D_MODEL
                                         + (kt + 1) * 64 + c4 * 4);
                bv[j] = *(const float4*)(W + (size_t)(bn + row) * D_MODEL
                                         + (kt + 1) * 64 + c4 * 4);
            }
        }

        const uint32_t sb  = s0 + (uint32_t)(kt & 1) * GSTG_B;
        const uint32_t sAh = sb;
        const uint32_t sWh = sb + 1 * GT_B;
        const uint32_t sWl = sb + 2 * GT_B;

#pragma unroll
        for (int ks = 0; ks < 4; ks++) {
            uint32_t ah[4][4], wh[2][4], wl[2][4];
            const uint32_t ka = (uint32_t)ks * 32;
#pragma unroll
            for (int mt = 0; mt < 4; mt++) {
                uint32_t ra = (uint32_t)((wm + mt * 16) * 144) + offA + ka;
                ldm_x4(ah[mt], sAh + ra);
            }
#pragma unroll
            for (int p = 0; p < 2; p++) {
                uint32_t rb = (uint32_t)((wn + p * 16) * 144) + offB + ka;
                ldm_x4(wh[p], sWh + rb);
                ldm_x4(wl[p], sWl + rb);
            }
#pragma unroll
            for (int mt = 0; mt < 4; mt++)
#pragma unroll
                for (int nt = 0; nt < 4; nt++) {
                    uint32_t h0 = wh[nt >> 1][(nt & 1) * 2];
                    uint32_t h1 = wh[nt >> 1][(nt & 1) * 2 + 1];
                    uint32_t l0 = wl[nt >> 1][(nt & 1) * 2];
                    uint32_t l1 = wl[nt >> 1][(nt & 1) * 2 + 1];
                    mma16816h(acc[mt][nt], ah[mt], h0, h1);
                    mma16816h(acc[mt][nt], ah[mt], l0, l1);
                }
        }

        if (kt < 15) {
            char* stg = sm + ((kt + 1) & 1) * GSTG_B;
#pragma unroll
            for (int j = 0; j < 8; j++) {
                int i = tid + j * 256;
                int row = i >> 4, c4 = i & 15;
                uint32_t ad = (uint32_t)(row * 144 + c4 * 8);
                *(uint2*)(stg + 0 * GT_B + ad) = pack_f4h(av[j]);
                uint2 hi, lo;
                split_f4h(bv[j], hi, lo);
                *(uint2*)(stg + 1 * GT_B + ad) = hi;
                *(uint2*)(stg + 2 * GT_B + ad) = lo;
            }
        }
        __syncthreads();
    }

#pragma unroll
    for (int mt = 0; mt < 4; mt++) {
        int row0 = bm + wm + mt * 16 + (lane >> 2);
#pragma unroll
        for (int nt = 0; nt < 4; nt++) {
            int col = bn + wn + nt * 8 + (lane & 3) * 2;
            float2 b2 = *(const float2*)&bias[col];
            float2 o0 = make_float2(acc[mt][nt][0] + b2.x, acc[mt][nt][1] + b2.y);
            float2 o1 = make_float2(acc[mt][nt][2] + b2.x, acc[mt][nt][3] + b2.y);
            *(float2*)(C + (size_t)row0 * D_MODEL + col) = o0;
            *(float2*)(C + (size_t)(row0 + 8) * D_MODEL + col) = o1;
        }
    }
}

// ---------------------------------------------------------------------------
// Flash attention via bf16x3 mma.sync — EXACT R4 kernel (frozen).
// 128 thr, 4 warps x 32 q-rows, BN=64 KV tile.
// ---------------------------------------------------------------------------
#define AQH 0
#define AQL 18432
#define AKH 36864
#define AKL 46080
#define AVH 55296
#define AVL 64512
#define A_SMEM 73728

__global__ __launch_bounds__(128)
void attn_mma(const float* __restrict__ Qg, const float* __restrict__ Kg,
              const float* __restrict__ Vg, float* __restrict__ Og)
{
    extern __shared__ char sm[];
    const uint32_t s0 = smem_u32(sm);

    const int tid  = threadIdx.x;
    const int lane = tid & 31;
    const int wid  = tid >> 5;
    const int qt = blockIdx.x;          // 16 q-tiles
    const int bh = blockIdx.y;          // 64 (b,h)
    const int b = bh >> 4, h = bh & 15;

    const size_t tok0 = (size_t)b * SEQ + qt * 128;
    const float* Qb = Qg + tok0 * D_MODEL + h * 64;
    const float* Kb = Kg + (size_t)b * SEQ * D_MODEL + h * 64;
    const float* Vb = Vg + (size_t)b * SEQ * D_MODEL + h * 64;

    const uint32_t laneA = (uint32_t)(((lane >> 3) & 1) * 8 + (lane & 7)) * 144
                         + (uint32_t)(lane >> 4) * 16;
    const uint32_t laneB = (uint32_t)((lane >> 4) * 8 + (lane & 7)) * 144
                         + (uint32_t)((lane >> 3) & 1) * 16;
    const uint32_t wq = (uint32_t)wid * 32 * 144;

    for (int i = tid; i < 128 * 16; i += 128) {
        int row = i >> 4, c4 = i & 15;
        float4 v = *(const float4*)(Qb + (size_t)row * D_MODEL + c4 * 4);
        uint2 hi, lo;
        split_f4(v, hi, lo);
        uint32_t ad = (uint32_t)(row * 144 + c4 * 8);
        *(uint2*)(sm + AQH + ad) = hi;
        *(uint2*)(sm + AQL + ad) = lo;
    }

    float o[2][8][4];
#pragma unroll
    for (int mt = 0; mt < 2; mt++)
#pragma unroll
        for (int dn = 0; dn < 8; dn++)
#pragma unroll
            for (int q = 0; q < 4; q++) o[mt][dn][q] = 0.f;
    float mrow[4] = {-1e30f, -1e30f, -1e30f, -1e30f};
    float lrow[4] = {0.f, 0.f, 0.f, 0.f};

    const float SC = 0.125f;

    for (int kt = 0; kt < SEQ / 64; kt++) {
        __syncthreads();
        for (int i = tid; i < 64 * 16; i += 128) {
            int row = i >> 4, c4 = i & 15;
            size_t gro = (size_t)(kt * 64 + row) * D_MODEL + c4 * 4;
            uint32_t ad = (uint32_t)(row * 144 + c4 * 8);
            uint2 hi, lo;
            split_f4(*(const float4*)(Kb + gro), hi, lo);
            *(uint2*)(sm + AKH + ad) = hi;
            *(uint2*)(sm + AKL + ad) = lo;
            split_f4(*(const float4*)(Vb + gro), hi, lo);
            *(uint2*)(sm + AVH + ad) = hi;
            *(uint2*)(sm + AVL + ad) = lo;
        }
        __syncthreads();

        float s[2][8][4];
#pragma unroll
        for (int mt = 0; mt < 2; mt++)
#pragma unroll
            for (int nt = 0; nt < 8; nt++)
#pragma unroll
                for (int q = 0; q < 4; q++) s[mt][nt][q] = 0.f;

#pragma unroll
        for (int k = 0; k < 4; k++) {
            uint32_t bhf[4][4], blf[4][4];
#pragma unroll
            for (int np = 0; np < 4; np++) {
                uint32_t rb = (uint32_t)(np * 16 * 144) + k * 32 + laneB;
                ldm_x4(bhf[np], s0 + AKH + rb);
                ldm_x4(blf[np], s0 + AKL + rb);
            }
#pragma unroll
            for (int mt = 0; mt < 2; mt++) {
                uint32_t ah[4], al[4];
                uint32_t ra = wq + (uint32_t)(mt * 16 * 144) + k * 32 + laneA;
                ldm_x4(ah, s0 + AQH + ra);
                ldm_x4(al, s0 + AQL + ra);
#pragma unroll
                for (int nt = 0; nt < 8; nt++) {
                    uint32_t h0 = bhf[nt >> 1][(nt & 1) * 2];
                    uint32_t h1 = bhf[nt >> 1][(nt & 1) * 2 + 1];
                    uint32_t l0 = blf[nt >> 1][(nt & 1) * 2];
                    uint32_t l1 = blf[nt >> 1][(nt & 1) * 2 + 1];
                    mma16816(s[mt][nt], ah, h0, h1);
                    mma16816(s[mt][nt], ah, l0, l1);
                    mma16816(s[mt][nt], al, h0, h1);
                }
            }
        }

        float corr[4];
#pragma unroll
        for (int rr = 0; rr < 4; rr++) {
            int mt = rr >> 1, c0 = (rr & 1) * 2;
            float mx = -1e30f;
#pragma unroll
            for (int nt = 0; nt < 8; nt++)
                mx = fmaxf(mx, fmaxf(s[mt][nt][c0], s[mt][nt][c0 + 1]));
            mx = fmaxf(mx, __shfl_xor_sync(0xffffffffu, mx, 1));
            mx = fmaxf(mx, __shfl_xor_sync(0xffffffffu, mx, 2));
            float mn = fmaxf(mrow[rr], mx);
            corr[rr] = __expf((mrow[rr] - mn) * SC);
            mrow[rr] = mn;
            float rs = 0.f;
#pragma unroll
            for (int nt = 0; nt < 8; nt++) {
                float e0 = __expf((s[mt][nt][c0] - mn) * SC);
                float e1 = __expf((s[mt][nt][c0 + 1] - mn) * SC);
                s[mt][nt][c0] = e0; s[mt][nt][c0 + 1] = e1;
                rs += e0 + e1;
            }
            rs += __shfl_xor_sync(0xffffffffu, rs, 1);
            rs += __shfl_xor_sync(0xffffffffu, rs, 2);
            lrow[rr] = lrow[rr] * corr[rr] + rs;
        }
#pragma unroll
        for (int mt = 0; mt < 2; mt++)
#pragma unroll
            for (int dn = 0; dn < 8; dn++) {
                o[mt][dn][0] *= corr[mt * 2];
                o[mt][dn][1] *= corr[mt * 2];
                o[mt][dn][2] *= corr[mt * 2 + 1];
                o[mt][dn][3] *= corr[mt * 2 + 1];
            }

#pragma unroll
        for (int kk = 0; kk < 4; kk++) {
            uint32_t vhf[4][4], vlf[4][4];
#pragma unroll
            for (int dp = 0; dp < 4; dp++) {
                uint32_t rv = (uint32_t)(kk * 16 * 144) + dp * 32 + laneA;
                ldm_x4_t(vhf[dp], s0 + AVH + rv);
                ldm_x4_t(vlf[dp], s0 + AVL + rv);
            }
#pragma unroll
            for (int mt = 0; mt < 2; mt++) {
                uint32_t ah[4], al[4];
                split2(s[mt][2 * kk][0],     s[mt][2 * kk][1],     ah[0], al[0]);
                split2(s[mt][2 * kk][2],     s[mt][2 * kk][3],     ah[1], al[1]);
                split2(s[mt][2 * kk + 1][0], s[mt][2 * kk + 1][1], ah[2], al[2]);
                split2(s[mt][2 * kk + 1][2], s[mt][2 * kk + 1][3], ah[3], al[3]);
#pragma unroll
                for (int dn = 0; dn < 8; dn++) {
                    uint32_t h0 = vhf[dn >> 1][(dn & 1) * 2];
                    uint32_t h1 = vhf[dn >> 1][(dn & 1) * 2 + 1];
                    uint32_t l0 = vlf[dn >> 1][(dn & 1) * 2];
                    uint32_t l1 = vlf[dn >> 1][(dn & 1) * 2 + 1];
                    mma16816(o[mt][dn], ah, h0, h1);
                    mma16816(o[mt][dn], ah, l0, l1);
                    mma16816(o[mt][dn], al, h0, h1);
                }
            }
        }
    }

    float inv[4];
#pragma unroll
    for (int rr = 0; rr < 4; rr++) inv[rr] = 1.f / lrow[rr];
#pragma unroll
    for (int mt = 0; mt < 2; mt++) {
        size_t row0 = tok0 + wid * 32 + mt * 16 + (lane >> 2);
#pragma unroll
        for (int dn = 0; dn < 8; dn++) {
            int col = h * 64 + dn * 8 + (lane & 3) * 2;
            float2 o0 = make_float2(o[mt][dn][0] * inv[mt * 2],
                                    o[mt][dn][1] * inv[mt * 2]);
            float2 o1 = make_float2(o[mt][dn][2] * inv[mt * 2 + 1],
                                    o[mt][dn][3] * inv[mt * 2 + 1]);
            *(float2*)(Og + row0 * D_MODEL + col) = o0;
            *(float2*)(Og + (row0 + 8) * D_MODEL + col) = o1;
        }
    }
}

// ---------------------------------------------------------------------------
extern "C" void kernel_launch(void* const* d_in, const int* in_sizes, int n_in,
                              void* d_out, int out_size)
{
    const float* q  = (const float*)d_in[0];
    const float* k  = (const float*)d_in[1];
    const float* v  = (const float*)d_in[2];
    const float* Wq = (const float*)d_in[3];
    const float* bq = (const float*)d_in[4];
    const float* Wk = (const float*)d_in[5];
    const float* bk = (const float*)d_in[6];
    const float* Wv = (const float*)d_in[7];
    const float* bv = (const float*)d_in[8];
    const float* Wo = (const float*)d_in[9];
    const float* bo = (const float*)d_in[10];
    float* out = (float*)d_out;

    float *gq, *gk, *gv, *ga;
    cudaGetSymbolAddress((void**)&gq, g_q);
    cudaGetSymbolAddress((void**)&gk, g_k);
    cudaGetSymbolAddress((void**)&gv, g_v);
    cudaGetSymbolAddress((void**)&ga, g_att);

    cudaFuncSetAttribute(gemm_f16x2,
                         cudaFuncAttributeMaxDynamicSharedMemorySize, GSM_B);
    cudaFuncSetAttribute(attn_mma,
                         cudaFuncAttributeMaxDynamicSharedMemorySize, A_SMEM);

    // fused Q/K/V projections: grid.z picks the problem instance
    dim3 pgrid(D_MODEL / 128, NTOK / 128, 3);
    gemm_f16x2<<<pgrid, 256, GSM_B>>>(q, Wq, bq, gq,
                                      k, Wk, bk, gk,
                                      v, Wv, bv, gv);

    attn_mma<<<dim3(SEQ / 128, BATCH * NHEAD), 128, A_SMEM>>>(gq, gk, gv, ga);

    dim3 ogrid(D_MODEL / 128, NTOK / 128, 1);
    gemm_f16x2<<<ogrid, 256, GSM_B>>>(ga, Wo, bo, out,
                                      ga, Wo, bo, out,
                                      ga, Wo, bo, out);
}

// round 10
// speedup vs baseline: 1.4140x; 1.3122x over previous
#include <cuda_runtime.h>
#include <cuda_bf16.h>
#include <cuda_fp16.h>
#include <cstdint>

#define D_MODEL 1024
#define NHEAD   16
#define HDIM    64
#define BATCH   4
#define SEQ     2048
#define NTOK    (BATCH*SEQ)

// Scratch (allocation-free per harness rules)
__device__ float g_q[(size_t)NTOK * D_MODEL];
__device__ float g_k[(size_t)NTOK * D_MODEL];
__device__ float g_v[(size_t)NTOK * D_MODEL];
__device__ float g_att[(size_t)NTOK * D_MODEL];

// ---------------------------------------------------------------------------
// helpers
// ---------------------------------------------------------------------------
__device__ __forceinline__ uint32_t smem_u32(const void* p) {
    uint32_t a;
    asm("{ .reg .u64 t; cvta.to.shared.u64 t, %1; cvt.u32.u64 %0, t; }"
        : "=r"(a) : "l"(p));
    return a;
}
__device__ __forceinline__ void ldm_x4(uint32_t r[4], uint32_t addr) {
    asm volatile("ldmatrix.sync.aligned.m8n8.x4.shared.b16 {%0,%1,%2,%3}, [%4];"
                 : "=r"(r[0]), "=r"(r[1]), "=r"(r[2]), "=r"(r[3]) : "r"(addr));
}
__device__ __forceinline__ void ldm_x4_t(uint32_t r[4], uint32_t addr) {
    asm volatile("ldmatrix.sync.aligned.m8n8.x4.trans.shared.b16 {%0,%1,%2,%3}, [%4];"
                 : "=r"(r[0]), "=r"(r[1]), "=r"(r[2]), "=r"(r[3]) : "r"(addr));
}
// fp16 mma (GEMMs + attention)
__device__ __forceinline__ void mma16816h(float c[4], const uint32_t a[4],
                                          uint32_t b0, uint32_t b1) {
    asm volatile(
        "mma.sync.aligned.m16n8k16.row.col.f32.f16.f16.f32 "
        "{%0,%1,%2,%3}, {%4,%5,%6,%7}, {%8,%9}, {%0,%1,%2,%3};"
        : "+f"(c[0]), "+f"(c[1]), "+f"(c[2]), "+f"(c[3])
        : "r"(a[0]), "r"(a[1]), "r"(a[2]), "r"(a[3]), "r"(b0), "r"(b1));
}
// fp16 split / pack
__device__ __forceinline__ void split2h(float f0, float f1,
                                        uint32_t& hi, uint32_t& lo) {
    __half2 h = __floats2half2_rn(f0, f1);
    float2 hf = __half22float2(h);
    __half2 l = __floats2half2_rn(f0 - hf.x, f1 - hf.y);
    hi = *(uint32_t*)&h; lo = *(uint32_t*)&l;
}
__device__ __forceinline__ void split_f4h(float4 v, uint2& hi, uint2& lo) {
    split2h(v.x, v.y, hi.x, lo.x);
    split2h(v.z, v.w, hi.y, lo.y);
}
__device__ __forceinline__ uint32_t pack2h(float f0, float f1) {
    __half2 h = __floats2half2_rn(f0, f1);
    return *(uint32_t*)&h;
}
__device__ __forceinline__ uint2 pack_f4h(float4 v) {
    uint2 r;
    r.x = pack2h(v.x, v.y);
    r.y = pack2h(v.z, v.w);
    return r;
}
__device__ __forceinline__ uint2 pack_f4h_scaled(float4 v, float sc) {
    uint2 r;
    r.x = pack2h(v.x * sc, v.y * sc);
    r.y = pack2h(v.z * sc, v.w * sc);
    return r;
}

// ---------------------------------------------------------------------------
// GEMM: C[8192,1024] = A @ W^T + bias  — fp16 2-pass (unchanged R9 winner).
// A single fp16, W split hi/lo. 128x128 tile, BK=64, 256 thr, double buffer.
// grid.z selects one of up to 3 (A,W,bias,C) problem instances.
// ---------------------------------------------------------------------------
#define GT_B    18432                // one tile: 128 rows * 144B
#define GSTG_B  (3 * GT_B)           // Ah | Wh | Wl = 55296
#define GSM_B   (2 * GSTG_B)         // 110592

__global__ __launch_bounds__(256, 1)
void gemm_f16x2(const float* __restrict__ A0, const float* __restrict__ W0,
                const float* __restrict__ b0_, float* __restrict__ C0,
                const float* __restrict__ A1, const float* __restrict__ W1,
                const float* __restrict__ b1_, float* __restrict__ C1,
                const float* __restrict__ A2, const float* __restrict__ W2,
                const float* __restrict__ b2_, float* __restrict__ C2)
{
    extern __shared__ char sm[];
    const uint32_t s0 = smem_u32(sm);

    const int z = blockIdx.z;
    const float* A    = (z == 0) ? A0  : (z == 1) ? A1  : A2;
    const float* W    = (z == 0) ? W0  : (z == 1) ? W1  : W2;
    const float* bias = (z == 0) ? b0_ : (z == 1) ? b1_ : b2_;
    float*       C    = (z == 0) ? C0  : (z == 1) ? C1  : C2;

    const int tid  = threadIdx.x;
    const int lane = tid & 31;
    const int wid  = tid >> 5;
    const int bm = blockIdx.y * 128;
    const int bn = blockIdx.x * 128;
    const int wm = (wid >> 2) * 64;
    const int wn = (wid & 3) * 32;

    float acc[4][4][4];
#pragma unroll
    for (int i = 0; i < 4; i++)
#pragma unroll
        for (int j = 0; j < 4; j++)
#pragma unroll
            for (int q = 0; q < 4; q++) acc[i][j][q] = 0.f;

    const uint32_t offA = (uint32_t)(lane & 15) * 144 + (uint32_t)(lane >> 4) * 16;
    const uint32_t offB = (uint32_t)((lane & 7) + ((lane >> 4) & 1) * 8) * 144
                        + (uint32_t)((lane >> 3) & 1) * 16;

    float4 av[8], bv[8];
#pragma unroll
    for (int j = 0; j < 8; j++) {
        int i = tid + j * 256;
        int row = i >> 4, c4 = i & 15;
        av[j] = *(const float4*)(A + (size_t)(bm + row) * D_MODEL + c4 * 4);
        bv[j] = *(const float4*)(W + (size_t)(bn + row) * D_MODEL + c4 * 4);
    }
    {
        char* stg = sm;
#pragma unroll
        for (int j = 0; j < 8; j++) {
            int i = tid + j * 256;
            int row = i >> 4, c4 = i & 15;
            uint32_t ad = (uint32_t)(row * 144 + c4 * 8);
            *(uint2*)(stg + 0 * GT_B + ad) = pack_f4h(av[j]);
            uint2 hi, lo;
            split_f4h(bv[j], hi, lo);
            *(uint2*)(stg + 1 * GT_B + ad) = hi;
            *(uint2*)(stg + 2 * GT_B + ad) = lo;
        }
    }
    __syncthreads();

    for (int kt = 0; kt < 16; kt++) {
        if (kt < 15) {
#pragma unroll
            for (int j = 0; j < 8; j++) {
                int i = tid + j * 256;
                int row = i >> 4, c4 = i & 15;
                av[j] = *(const float4*)(A + (size_t)(bm + row) * D_MODEL
                                         + (kt + 1) * 64 + c4 * 4);
                bv[j] = *(const float4*)(W + (size_t)(bn + row) * D_MODEL
                                         + (kt + 1) * 64 + c4 * 4);
            }
        }

        const uint32_t sb  = s0 + (uint32_t)(kt & 1) * GSTG_B;
        const uint32_t sAh = sb;
        const uint32_t sWh = sb + 1 * GT_B;
        const uint32_t sWl = sb + 2 * GT_B;

#pragma unroll
        for (int ks = 0; ks < 4; ks++) {
            uint32_t ah[4][4], wh[2][4], wl[2][4];
            const uint32_t ka = (uint32_t)ks * 32;
#pragma unroll
            for (int mt = 0; mt < 4; mt++) {
                uint32_t ra = (uint32_t)((wm + mt * 16) * 144) + offA + ka;
                ldm_x4(ah[mt], sAh + ra);
            }
#pragma unroll
            for (int p = 0; p < 2; p++) {
                uint32_t rb = (uint32_t)((wn + p * 16) * 144) + offB + ka;
                ldm_x4(wh[p], sWh + rb);
                ldm_x4(wl[p], sWl + rb);
            }
#pragma unroll
            for (int mt = 0; mt < 4; mt++)
#pragma unroll
                for (int nt = 0; nt < 4; nt++) {
                    uint32_t h0 = wh[nt >> 1][(nt & 1) * 2];
                    uint32_t h1 = wh[nt >> 1][(nt & 1) * 2 + 1];
                    uint32_t l0 = wl[nt >> 1][(nt & 1) * 2];
                    uint32_t l1 = wl[nt >> 1][(nt & 1) * 2 + 1];
                    mma16816h(acc[mt][nt], ah[mt], h0, h1);
                    mma16816h(acc[mt][nt], ah[mt], l0, l1);
                }
        }

        if (kt < 15) {
            char* stg = sm + ((kt + 1) & 1) * GSTG_B;
#pragma unroll
            for (int j = 0; j < 8; j++) {
                int i = tid + j * 256;
                int row = i >> 4, c4 = i & 15;
                uint32_t ad = (uint32_t)(row * 144 + c4 * 8);
                *(uint2*)(stg + 0 * GT_B + ad) = pack_f4h(av[j]);
                uint2 hi, lo;
                split_f4h(bv[j], hi, lo);
                *(uint2*)(stg + 1 * GT_B + ad) = hi;
                *(uint2*)(stg + 2 * GT_B + ad) = lo;
            }
        }
        __syncthreads();
    }

#pragma unroll
    for (int mt = 0; mt < 4; mt++) {
        int row0 = bm + wm + mt * 16 + (lane >> 2);
#pragma unroll
        for (int nt = 0; nt < 4; nt++) {
            int col = bn + wn + nt * 8 + (lane & 3) * 2;
            float2 b2 = *(const float2*)&bias[col];
            float2 o0 = make_float2(acc[mt][nt][0] + b2.x, acc[mt][nt][1] + b2.y);
            float2 o1 = make_float2(acc[mt][nt][2] + b2.x, acc[mt][nt][3] + b2.y);
            *(float2*)(C + (size_t)row0 * D_MODEL + col) = o0;
            *(float2*)(C + (size_t)(row0 + 8) * D_MODEL + col) = o1;
        }
    }
}

// ---------------------------------------------------------------------------
// Flash attention — fp16 reduced-pass version of the R4 structure.
// 128 thr, 4 warps x 32 q-rows, BN=64 KV tile.
// QK: 2-pass (Q single fp16 pre-scaled by 1/8; K split fp16 hi/lo).
// PV: 1-pass (P packed fp16; V single fp16).
// smem: Q[128][72]h, Kh/Kl[64][72]h, V[64][72]h = 46 KB.
// ---------------------------------------------------------------------------
#define AQ  0
#define AKH 18432
#define AKL 27648
#define AV  36864
#define A_SMEM 46080

__global__ __launch_bounds__(128)
void attn_mma(const float* __restrict__ Qg, const float* __restrict__ Kg,
              const float* __restrict__ Vg, float* __restrict__ Og)
{
    extern __shared__ char sm[];
    const uint32_t s0 = smem_u32(sm);

    const int tid  = threadIdx.x;
    const int lane = tid & 31;
    const int wid  = tid >> 5;
    const int qt = blockIdx.x;          // 16 q-tiles
    const int bh = blockIdx.y;          // 64 (b,h)
    const int b = bh >> 4, h = bh & 15;

    const size_t tok0 = (size_t)b * SEQ + qt * 128;
    const float* Qb = Qg + tok0 * D_MODEL + h * 64;
    const float* Kb = Kg + (size_t)b * SEQ * D_MODEL + h * 64;
    const float* Vb = Vg + (size_t)b * SEQ * D_MODEL + h * 64;

    const uint32_t laneA = (uint32_t)(((lane >> 3) & 1) * 8 + (lane & 7)) * 144
                         + (uint32_t)(lane >> 4) * 16;   // A frags (Q) and V trans
    const uint32_t laneB = (uint32_t)((lane >> 4) * 8 + (lane & 7)) * 144
                         + (uint32_t)((lane >> 3) & 1) * 16;  // B frags (K)
    const uint32_t wq = (uint32_t)wid * 32 * 144;

    // load Q tile (128 x 64 fp32), pre-scale by 1/sqrt(Dh)=0.125 (exact), fp16
    for (int i = tid; i < 128 * 16; i += 128) {
        int row = i >> 4, c4 = i & 15;
        float4 v = *(const float4*)(Qb + (size_t)row * D_MODEL + c4 * 4);
        uint32_t ad = (uint32_t)(row * 144 + c4 * 8);
        *(uint2*)(sm + AQ + ad) = pack_f4h_scaled(v, 0.125f);
    }

    float o[2][8][4];
#pragma unroll
    for (int mt = 0; mt < 2; mt++)
#pragma unroll
        for (int dn = 0; dn < 8; dn++)
#pragma unroll
            for (int q = 0; q < 4; q++) o[mt][dn][q] = 0.f;
    float mrow[4] = {-1e30f, -1e30f, -1e30f, -1e30f};
    float lrow[4] = {0.f, 0.f, 0.f, 0.f};

    for (int kt = 0; kt < SEQ / 64; kt++) {
        __syncthreads();   // previous tile's smem reads complete
        // load K (split fp16 hi/lo) and V (single fp16)
        for (int i = tid; i < 64 * 16; i += 128) {
            int row = i >> 4, c4 = i & 15;
            size_t gro = (size_t)(kt * 64 + row) * D_MODEL + c4 * 4;
            uint32_t ad = (uint32_t)(row * 144 + c4 * 8);
            uint2 hi, lo;
            split_f4h(*(const float4*)(Kb + gro), hi, lo);
            *(uint2*)(sm + AKH + ad) = hi;
            *(uint2*)(sm + AKL + ad) = lo;
            *(uint2*)(sm + AV + ad) = pack_f4h(*(const float4*)(Vb + gro));
        }
        __syncthreads();

        // ---- S = Q @ K^T (2-pass: qh*kh + qh*kl); scores pre-scaled
        float s[2][8][4];
#pragma unroll
        for (int mt = 0; mt < 2; mt++)
#pragma unroll
            for (int nt = 0; nt < 8; nt++)
#pragma unroll
                for (int q = 0; q < 4; q++) s[mt][nt][q] = 0.f;

#pragma unroll
        for (int k = 0; k < 4; k++) {
            uint32_t bhf[4][4], blf[4][4];
#pragma unroll
            for (int np = 0; np < 4; np++) {
                uint32_t rb = (uint32_t)(np * 16 * 144) + k * 32 + laneB;
                ldm_x4(bhf[np], s0 + AKH + rb);
                ldm_x4(blf[np], s0 + AKL + rb);
            }
#pragma unroll
            for (int mt = 0; mt < 2; mt++) {
                uint32_t ah[4];
                uint32_t ra = wq + (uint32_t)(mt * 16 * 144) + k * 32 + laneA;
                ldm_x4(ah, s0 + AQ + ra);
#pragma unroll
                for (int nt = 0; nt < 8; nt++) {
                    uint32_t h0 = bhf[nt >> 1][(nt & 1) * 2];
                    uint32_t h1 = bhf[nt >> 1][(nt & 1) * 2 + 1];
                    uint32_t l0 = blf[nt >> 1][(nt & 1) * 2];
                    uint32_t l1 = blf[nt >> 1][(nt & 1) * 2 + 1];
                    mma16816h(s[mt][nt], ah, h0, h1);
                    mma16816h(s[mt][nt], ah, l0, l1);
                }
            }
        }

        // ---- online softmax (scores already scaled; no SC multiplies)
        float corr[4];
#pragma unroll
        for (int rr = 0; rr < 4; rr++) {
            int mt = rr >> 1, c0 = (rr & 1) * 2;
            float mx = -1e30f;
#pragma unroll
            for (int nt = 0; nt < 8; nt++)
                mx = fmaxf(mx, fmaxf(s[mt][nt][c0], s[mt][nt][c0 + 1]));
            mx = fmaxf(mx, __shfl_xor_sync(0xffffffffu, mx, 1));
            mx = fmaxf(mx, __shfl_xor_sync(0xffffffffu, mx, 2));
            float mn = fmaxf(mrow[rr], mx);
            corr[rr] = __expf(mrow[rr] - mn);
            mrow[rr] = mn;
            float rs = 0.f;
#pragma unroll
            for (int nt = 0; nt < 8; nt++) {
                float e0 = __expf(s[mt][nt][c0] - mn);
                float e1 = __expf(s[mt][nt][c0 + 1] - mn);
                s[mt][nt][c0] = e0; s[mt][nt][c0 + 1] = e1;
                rs += e0 + e1;
            }
            rs += __shfl_xor_sync(0xffffffffu, rs, 1);
            rs += __shfl_xor_sync(0xffffffffu, rs, 2);
            lrow[rr] = lrow[rr] * corr[rr] + rs;
        }
#pragma unroll
        for (int mt = 0; mt < 2; mt++)
#pragma unroll
            for (int dn = 0; dn < 8; dn++) {
                o[mt][dn][0] *= corr[mt * 2];
                o[mt][dn][1] *= corr[mt * 2];
                o[mt][dn][2] *= corr[mt * 2 + 1];
                o[mt][dn][3] *= corr[mt * 2 + 1];
            }

        // ---- O += P @ V (1-pass: P fp16, V fp16)
#pragma unroll
        for (int kk = 0; kk < 4; kk++) {
            uint32_t vhf[4][4];
#pragma unroll
            for (int dp = 0; dp < 4; dp++) {
                uint32_t rv = (uint32_t)(kk * 16 * 144) + dp * 32 + laneA;
                ldm_x4_t(vhf[dp], s0 + AV + rv);
            }
#pragma unroll
            for (int mt = 0; mt < 2; mt++) {
                uint32_t ph[4];
                ph[0] = pack2h(s[mt][2 * kk][0],     s[mt][2 * kk][1]);
                ph[1] = pack2h(s[mt][2 * kk][2],     s[mt][2 * kk][3]);
                ph[2] = pack2h(s[mt][2 * kk + 1][0], s[mt][2 * kk + 1][1]);
                ph[3] = pack2h(s[mt][2 * kk + 1][2], s[mt][2 * kk + 1][3]);
#pragma unroll
                for (int dn = 0; dn < 8; dn++) {
                    uint32_t h0 = vhf[dn >> 1][(dn & 1) * 2];
                    uint32_t h1 = vhf[dn >> 1][(dn & 1) * 2 + 1];
                    mma16816h(o[mt][dn], ph, h0, h1);
                }
            }
        }
    }

    // ---- epilogue
    float inv[4];
#pragma unroll
    for (int rr = 0; rr < 4; rr++) inv[rr] = 1.f / lrow[rr];
#pragma unroll
    for (int mt = 0; mt < 2; mt++) {
        size_t row0 = tok0 + wid * 32 + mt * 16 + (lane >> 2);
#pragma unroll
        for (int dn = 0; dn < 8; dn++) {
            int col = h * 64 + dn * 8 + (lane & 3) * 2;
            float2 o0 = make_float2(o[mt][dn][0] * inv[mt * 2],
                                    o[mt][dn][1] * inv[mt * 2]);
            float2 o1 = make_float2(o[mt][dn][2] * inv[mt * 2 + 1],
                                    o[mt][dn][3] * inv[mt * 2 + 1]);
            *(float2*)(Og + row0 * D_MODEL + col) = o0;
            *(float2*)(Og + (row0 + 8) * D_MODEL + col) = o1;
        }
    }
}

// ---------------------------------------------------------------------------
extern "C" void kernel_launch(void* const* d_in, const int* in_sizes, int n_in,
                              void* d_out, int out_size)
{
    const float* q  = (const float*)d_in[0];
    const float* k  = (const float*)d_in[1];
    const float* v  = (const float*)d_in[2];
    const float* Wq = (const float*)d_in[3];
    const float* bq = (const float*)d_in[4];
    const float* Wk = (const float*)d_in[5];
    const float* bk = (const float*)d_in[6];
    const float* Wv = (const float*)d_in[7];
    const float* bv = (const float*)d_in[8];
    const float* Wo = (const float*)d_in[9];
    const float* bo = (const float*)d_in[10];
    float* out = (float*)d_out;

    float *gq, *gk, *gv, *ga;
    cudaGetSymbolAddress((void**)&gq, g_q);
    cudaGetSymbolAddress((void**)&gk, g_k);
    cudaGetSymbolAddress((void**)&gv, g_v);
    cudaGetSymbolAddress((void**)&ga, g_att);

    cudaFuncSetAttribute(gemm_f16x2,
                         cudaFuncAttributeMaxDynamicSharedMemorySize, GSM_B);
    cudaFuncSetAttribute(attn_mma,
                         cudaFuncAttributeMaxDynamicSharedMemorySize, A_SMEM);

    // fused Q/K/V projections: grid.z picks the problem instance
    dim3 pgrid(D_MODEL / 128, NTOK / 128, 3);
    gemm_f16x2<<<pgrid, 256, GSM_B>>>(q, Wq, bq, gq,
                                      k, Wk, bk, gk,
                                      v, Wv, bv, gv);

    attn_mma<<<dim3(SEQ / 128, BATCH * NHEAD), 128, A_SMEM>>>(gq, gk, gv, ga);

    dim3 ogrid(D_MODEL / 128, NTOK / 128, 1);
    gemm_f16x2<<<ogrid, 256, GSM_B>>>(ga, Wo, bo, out,
                                      ga, Wo, bo, out,
                                      ga, Wo, bo, out);
}

// round 11
// speedup vs baseline: 1.5222x; 1.0765x over previous
#include <cuda_runtime.h>
#include <cuda_fp16.h>
#include <cstdint>

#define D_MODEL 1024
#define NHEAD   16
#define HDIM    64
#define BATCH   4
#define SEQ     2048
#define NTOK    (BATCH*SEQ)

#define ACT_N ((size_t)NTOK * D_MODEL)
#define W_N   ((size_t)D_MODEL * D_MODEL)

// Scratch (allocation-free per harness rules) — all fp16 now
__device__ __half g_qin[ACT_N], g_kin[ACT_N], g_vin[ACT_N];
__device__ __half g_Wqh[W_N], g_Wql[W_N], g_Wkh[W_N], g_Wkl[W_N];
__device__ __half g_Wvh[W_N], g_Wvl[W_N], g_Woh[W_N], g_Wol[W_N];
__device__ __half g_Qp[ACT_N];                 // scaled by 1/8
__device__ __half g_Kph[ACT_N], g_Kpl[ACT_N];  // split hi/lo
__device__ __half g_Vp[ACT_N];
__device__ __half g_Att[ACT_N];

// ---------------------------------------------------------------------------
// helpers
// ---------------------------------------------------------------------------
__device__ __forceinline__ uint32_t smem_u32(const void* p) {
    uint32_t a;
    asm("{ .reg .u64 t; cvta.to.shared.u64 t, %1; cvt.u32.u64 %0, t; }"
        : "=r"(a) : "l"(p));
    return a;
}
__device__ __forceinline__ void ldm_x4(uint32_t r[4], uint32_t addr) {
    asm volatile("ldmatrix.sync.aligned.m8n8.x4.shared.b16 {%0,%1,%2,%3}, [%4];"
                 : "=r"(r[0]), "=r"(r[1]), "=r"(r[2]), "=r"(r[3]) : "r"(addr));
}
__device__ __forceinline__ void ldm_x4_t(uint32_t r[4], uint32_t addr) {
    asm volatile("ldmatrix.sync.aligned.m8n8.x4.trans.shared.b16 {%0,%1,%2,%3}, [%4];"
                 : "=r"(r[0]), "=r"(r[1]), "=r"(r[2]), "=r"(r[3]) : "r"(addr));
}
__device__ __forceinline__ void mma16816h(float c[4], const uint32_t a[4],
                                          uint32_t b0, uint32_t b1) {
    asm volatile(
        "mma.sync.aligned.m16n8k16.row.col.f32.f16.f16.f32 "
        "{%0,%1,%2,%3}, {%4,%5,%6,%7}, {%8,%9}, {%0,%1,%2,%3};"
        : "+f"(c[0]), "+f"(c[1]), "+f"(c[2]), "+f"(c[3])
        : "r"(a[0]), "r"(a[1]), "r"(a[2]), "r"(a[3]), "r"(b0), "r"(b1));
}
__device__ __forceinline__ void split2h(float f0, float f1,
                                        uint32_t& hi, uint32_t& lo) {
    __half2 h = __floats2half2_rn(f0, f1);
    float2 hf = __half22float2(h);
    __half2 l = __floats2half2_rn(f0 - hf.x, f1 - hf.y);
    hi = *(uint32_t*)&h; lo = *(uint32_t*)&l;
}
__device__ __forceinline__ uint32_t pack2h(float f0, float f1) {
    __half2 h = __floats2half2_rn(f0, f1);
    return *(uint32_t*)&h;
}

// ------------------------- producer conversion kernels ----------------------
__global__ void cvt_f16(const float* __restrict__ x0, __half* __restrict__ y0,
                        const float* __restrict__ x1, __half* __restrict__ y1,
                        const float* __restrict__ x2, __half* __restrict__ y2,
                        int n4)
{
    const float* x = (blockIdx.z == 0) ? x0 : (blockIdx.z == 1) ? x1 : x2;
    __half*      y = (blockIdx.z == 0) ? y0 : (blockIdx.z == 1) ? y1 : y2;
    int i = blockIdx.x * blockDim.x + threadIdx.x;
    int stride = gridDim.x * blockDim.x;
    for (; i < n4; i += stride) {
        float4 v = ((const float4*)x)[i];
        uint2 r;
        r.x = pack2h(v.x, v.y);
        r.y = pack2h(v.z, v.w);
        ((uint2*)y)[i] = r;
    }
}

__global__ void wsplit_f16(const float* __restrict__ x0, __half* __restrict__ h0, __half* __restrict__ l0,
                           const float* __restrict__ x1, __half* __restrict__ h1, __half* __restrict__ l1,
                           const float* __restrict__ x2, __half* __restrict__ h2, __half* __restrict__ l2,
                           const float* __restrict__ x3, __half* __restrict__ h3, __half* __restrict__ l3,
                           int n4)
{
    int z = blockIdx.z;
    const float* x = (z == 0) ? x0 : (z == 1) ? x1 : (z == 2) ? x2 : x3;
    __half*     yh = (z == 0) ? h0 : (z == 1) ? h1 : (z == 2) ? h2 : h3;
    __half*     yl = (z == 0) ? l0 : (z == 1) ? l1 : (z == 2) ? l2 : l3;
    int i = blockIdx.x * blockDim.x + threadIdx.x;
    int stride = gridDim.x * blockDim.x;
    for (; i < n4; i += stride) {
        float4 v = ((const float4*)x)[i];
        uint2 h, l;
        split2h(v.x, v.y, h.x, l.x);
        split2h(v.z, v.w, h.y, l.y);
        ((uint2*)yh)[i] = h;
        ((uint2*)yl)[i] = l;
    }
}

// ---------------------------------------------------------------------------
// GEMM: C[8192,1024] = A @ W^T + bias — fp16 2-pass, all-fp16 inputs.
// A single fp16, W pre-split hi/lo. 128x128 tile, BK=64, 256 thr, 2-stage.
// Epilogue mode = base_mode + z:
//   0: fp32 out (+bias)          1: fp16 out scaled 1/8 (+bias)   [Q]
//   2: fp16 split hi/lo (+bias)  [K]
//   3: fp16 out (+bias)          [V]
// ---------------------------------------------------------------------------
#define GT_B    18432                // one tile: 128 rows * 144B
#define GSTG_B  (3 * GT_B)           // A | Wh | Wl = 55296
#define GSM_B   (2 * GSTG_B)         // 110592

__global__ __launch_bounds__(256, 1)
void gemm_f16(const __half* __restrict__ A0, const __half* __restrict__ Wh0,
              const __half* __restrict__ Wl0, const float* __restrict__ b0_,
              void* O0a, void* O0b,
              const __half* __restrict__ A1, const __half* __restrict__ Wh1,
              const __half* __restrict__ Wl1, const float* __restrict__ b1_,
              void* O1a, void* O1b,
              const __half* __restrict__ A2, const __half* __restrict__ Wh2,
              const __half* __restrict__ Wl2, const float* __restrict__ b2_,
              void* O2a, void* O2b,
              int base_mode)
{
    extern __shared__ char sm[];
    const uint32_t s0 = smem_u32(sm);

    const int z = blockIdx.z;
    const __half* A    = (z == 0) ? A0  : (z == 1) ? A1  : A2;
    const __half* Wh   = (z == 0) ? Wh0 : (z == 1) ? Wh1 : Wh2;
    const __half* Wl   = (z == 0) ? Wl0 : (z == 1) ? Wl1 : Wl2;
    const float*  bias = (z == 0) ? b0_ : (z == 1) ? b1_ : b2_;
    void* Oa = (z == 0) ? O0a : (z == 1) ? O1a : O2a;
    void* Ob = (z == 0) ? O0b : (z == 1) ? O1b : O2b;
    const int mode = base_mode + z;

    const int tid  = threadIdx.x;
    const int lane = tid & 31;
    const int wid  = tid >> 5;
    const int bm = blockIdx.y * 128;
    const int bn = blockIdx.x * 128;
    const int wm = (wid >> 2) * 64;
    const int wn = (wid & 3) * 32;

    float acc[4][4][4];
#pragma unroll
    for (int i = 0; i < 4; i++)
#pragma unroll
        for (int j = 0; j < 4; j++)
#pragma unroll
            for (int q = 0; q < 4; q++) acc[i][j][q] = 0.f;

    const uint32_t offA = (uint32_t)(lane & 15) * 144 + (uint32_t)(lane >> 4) * 16;
    const uint32_t offB = (uint32_t)((lane & 7) + ((lane >> 4) & 1) * 8) * 144
                        + (uint32_t)((lane >> 3) & 1) * 16;

    // per-thread: 4 chunks of A, 4 of Wh, 4 of Wl (16B each)
    uint4 aw[4], whw[4], wlw[4];
#pragma unroll
    for (int j = 0; j < 4; j++) {
        int c = tid + j * 256;
        int row = c >> 3, seg = c & 7;
        aw[j]  = *(const uint4*)(A  + (size_t)(bm + row) * D_MODEL + seg * 8);
        whw[j] = *(const uint4*)(Wh + (size_t)(bn + row) * D_MODEL + seg * 8);
        wlw[j] = *(const uint4*)(Wl + (size_t)(bn + row) * D_MODEL + seg * 8);
    }
    {
        char* stg = sm;
#pragma unroll
        for (int j = 0; j < 4; j++) {
            int c = tid + j * 256;
            int row = c >> 3, seg = c & 7;
            uint32_t ad = (uint32_t)(row * 144 + seg * 16);
            *(uint4*)(stg + 0 * GT_B + ad) = aw[j];
            *(uint4*)(stg + 1 * GT_B + ad) = whw[j];
            *(uint4*)(stg + 2 * GT_B + ad) = wlw[j];
        }
    }
    __syncthreads();

    for (int kt = 0; kt < 16; kt++) {
        if (kt < 15) {
            const int k0 = (kt + 1) * 64;
#pragma unroll
            for (int j = 0; j < 4; j++) {
                int c = tid + j * 256;
                int row = c >> 3, seg = c & 7;
                aw[j]  = *(const uint4*)(A  + (size_t)(bm + row) * D_MODEL + k0 + seg * 8);
                whw[j] = *(const uint4*)(Wh + (size_t)(bn + row) * D_MODEL + k0 + seg * 8);
                wlw[j] = *(const uint4*)(Wl + (size_t)(bn + row) * D_MODEL + k0 + seg * 8);
            }
        }

        const uint32_t sb  = s0 + (uint32_t)(kt & 1) * GSTG_B;
        const uint32_t sA  = sb;
        const uint32_t sWh = sb + 1 * GT_B;
        const uint32_t sWl = sb + 2 * GT_B;

#pragma unroll
        for (int ks = 0; ks < 4; ks++) {
            uint32_t ah[4][4], wh[2][4], wl[2][4];
            const uint32_t ka = (uint32_t)ks * 32;
#pragma unroll
            for (int mt = 0; mt < 4; mt++) {
                uint32_t ra = (uint32_t)((wm + mt * 16) * 144) + offA + ka;
                ldm_x4(ah[mt], sA + ra);
            }
#pragma unroll
            for (int p = 0; p < 2; p++) {
                uint32_t rb = (uint32_t)((wn + p * 16) * 144) + offB + ka;
                ldm_x4(wh[p], sWh + rb);
                ldm_x4(wl[p], sWl + rb);
            }
#pragma unroll
            for (int mt = 0; mt < 4; mt++)
#pragma unroll
                for (int nt = 0; nt < 4; nt++) {
                    uint32_t h0 = wh[nt >> 1][(nt & 1) * 2];
                    uint32_t h1 = wh[nt >> 1][(nt & 1) * 2 + 1];
                    uint32_t l0 = wl[nt >> 1][(nt & 1) * 2];
                    uint32_t l1 = wl[nt >> 1][(nt & 1) * 2 + 1];
                    mma16816h(acc[mt][nt], ah[mt], h0, h1);
                    mma16816h(acc[mt][nt], ah[mt], l0, l1);
                }
        }

        if (kt < 15) {
            char* stg = sm + ((kt + 1) & 1) * GSTG_B;
#pragma unroll
            for (int j = 0; j < 4; j++) {
                int c = tid + j * 256;
                int row = c >> 3, seg = c & 7;
                uint32_t ad = (uint32_t)(row * 144 + seg * 16);
                *(uint4*)(stg + 0 * GT_B + ad) = aw[j];
                *(uint4*)(stg + 1 * GT_B + ad) = whw[j];
                *(uint4*)(stg + 2 * GT_B + ad) = wlw[j];
            }
        }
        __syncthreads();
    }

    // ---- epilogue (mode-dependent output format)
#pragma unroll
    for (int mt = 0; mt < 4; mt++) {
        int row0 = bm + wm + mt * 16 + (lane >> 2);
#pragma unroll
        for (int nt = 0; nt < 4; nt++) {
            int col = bn + wn + nt * 8 + (lane & 3) * 2;
            float2 b2 = *(const float2*)&bias[col];
            float c0 = acc[mt][nt][0] + b2.x, c1 = acc[mt][nt][1] + b2.y;
            float c2 = acc[mt][nt][2] + b2.x, c3 = acc[mt][nt][3] + b2.y;
            size_t i0 = (size_t)row0 * D_MODEL + col;
            size_t i1 = (size_t)(row0 + 8) * D_MODEL + col;
            if (mode == 0) {
                *(float2*)((float*)Oa + i0) = make_float2(c0, c1);
                *(float2*)((float*)Oa + i1) = make_float2(c2, c3);
            } else if (mode == 1) {       // Q: scaled fp16
                *(uint32_t*)((__half*)Oa + i0) = pack2h(c0 * 0.125f, c1 * 0.125f);
                *(uint32_t*)((__half*)Oa + i1) = pack2h(c2 * 0.125f, c3 * 0.125f);
            } else if (mode == 2) {       // K: split hi/lo
                uint32_t h, l;
                split2h(c0, c1, h, l);
                *(uint32_t*)((__half*)Oa + i0) = h;
                *(uint32_t*)((__half*)Ob + i0) = l;
                split2h(c2, c3, h, l);
                *(uint32_t*)((__half*)Oa + i1) = h;
                *(uint32_t*)((__half*)Ob + i1) = l;
            } else {                       // V / attn-out: plain fp16
                *(uint32_t*)((__half*)Oa + i0) = pack2h(c0, c1);
                *(uint32_t*)((__half*)Oa + i1) = pack2h(c2, c3);
            }
        }
    }
}

// ---------------------------------------------------------------------------
// Flash attention — R10 mainloop (frozen), inputs pre-formatted fp16:
// Qp (scaled 1/8), Kh/Kl (split), Vp. Output fp16 for the Wo GEMM.
// 128 thr, 4 warps x 32 q-rows, BN=64 KV tile.
// ---------------------------------------------------------------------------
#define AQ  0
#define AKH 18432
#define AKL 27648
#define AV  36864
#define A_SMEM 46080

__global__ __launch_bounds__(128)
void attn_mma(const __half* __restrict__ Qp, const __half* __restrict__ Kh_,
              const __half* __restrict__ Kl_, const __half* __restrict__ Vp,
              __half* __restrict__ Og)
{
    extern __shared__ char sm[];
    const uint32_t s0 = smem_u32(sm);

    const int tid  = threadIdx.x;
    const int lane = tid & 31;
    const int wid  = tid >> 5;
    const int qt = blockIdx.x;          // 16 q-tiles
    const int bh = blockIdx.y;          // 64 (b,h)
    const int b = bh >> 4, h = bh & 15;

    const size_t tok0 = (size_t)b * SEQ + qt * 128;
    const __half* Qb  = Qp  + tok0 * D_MODEL + h * 64;
    const __half* Khb = Kh_ + (size_t)b * SEQ * D_MODEL + h * 64;
    const __half* Klb = Kl_ + (size_t)b * SEQ * D_MODEL + h * 64;
    const __half* Vb  = Vp  + (size_t)b * SEQ * D_MODEL + h * 64;

    const uint32_t laneA = (uint32_t)(((lane >> 3) & 1) * 8 + (lane & 7)) * 144
                         + (uint32_t)(lane >> 4) * 16;
    const uint32_t laneB = (uint32_t)((lane >> 4) * 8 + (lane & 7)) * 144
                         + (uint32_t)((lane >> 3) & 1) * 16;
    const uint32_t wq = (uint32_t)wid * 32 * 144;

    // load Q tile: pure 16B copies (1024 chunks / 128 thr = 8 iters)
#pragma unroll
    for (int j = 0; j < 8; j++) {
        int c = tid + j * 128;
        int row = c >> 3, seg = c & 7;
        *(uint4*)(sm + AQ + row * 144 + seg * 16) =
            *(const uint4*)(Qb + (size_t)row * D_MODEL + seg * 8);
    }

    float o[2][8][4];
#pragma unroll
    for (int mt = 0; mt < 2; mt++)
#pragma unroll
        for (int dn = 0; dn < 8; dn++)
#pragma unroll
            for (int q = 0; q < 4; q++) o[mt][dn][q] = 0.f;
    float mrow[4] = {-1e30f, -1e30f, -1e30f, -1e30f};
    float lrow[4] = {0.f, 0.f, 0.f, 0.f};

    for (int kt = 0; kt < SEQ / 64; kt++) {
        __syncthreads();
        // load Kh, Kl, V tiles: pure 16B copies (512 chunks each, 4 iters each)
        const size_t rb = (size_t)kt * 64 * D_MODEL;
#pragma unroll
        for (int j = 0; j < 4; j++) {
            int c = tid + j * 128;
            int row = c >> 3, seg = c & 7;
            size_t go = rb + (size_t)row * D_MODEL + seg * 8;
            uint32_t ad = (uint32_t)(row * 144 + seg * 16);
            *(uint4*)(sm + AKH + ad) = *(const uint4*)(Khb + go);
            *(uint4*)(sm + AKL + ad) = *(const uint4*)(Klb + go);
            *(uint4*)(sm + AV  + ad) = *(const uint4*)(Vb  + go);
        }
        __syncthreads();

        // ---- S = Q @ K^T (2-pass); scores pre-scaled
        float s[2][8][4];
#pragma unroll
        for (int mt = 0; mt < 2; mt++)
#pragma unroll
            for (int nt = 0; nt < 8; nt++)
#pragma unroll
                for (int q = 0; q < 4; q++) s[mt][nt][q] = 0.f;

#pragma unroll
        for (int k = 0; k < 4; k++) {
            uint32_t bhf[4][4], blf[4][4];
#pragma unroll
            for (int np = 0; np < 4; np++) {
                uint32_t rbb = (uint32_t)(np * 16 * 144) + k * 32 + laneB;
                ldm_x4(bhf[np], s0 + AKH + rbb);
                ldm_x4(blf[np], s0 + AKL + rbb);
            }
#pragma unroll
            for (int mt = 0; mt < 2; mt++) {
                uint32_t ah[4];
                uint32_t ra = wq + (uint32_t)(mt * 16 * 144) + k * 32 + laneA;
                ldm_x4(ah, s0 + AQ + ra);
#pragma unroll
                for (int nt = 0; nt < 8; nt++) {
                    uint32_t h0 = bhf[nt >> 1][(nt & 1) * 2];
                    uint32_t h1 = bhf[nt >> 1][(nt & 1) * 2 + 1];
                    uint32_t l0 = blf[nt >> 1][(nt & 1) * 2];
                    uint32_t l1 = blf[nt >> 1][(nt & 1) * 2 + 1];
                    mma16816h(s[mt][nt], ah, h0, h1);
                    mma16816h(s[mt][nt], ah, l0, l1);
                }
            }
        }

        // ---- online softmax
        float corr[4];
#pragma unroll
        for (int rr = 0; rr < 4; rr++) {
            int mt = rr >> 1, c0 = (rr & 1) * 2;
            float mx = -1e30f;
#pragma unroll
            for (int nt = 0; nt < 8; nt++)
                mx = fmaxf(mx, fmaxf(s[mt][nt][c0], s[mt][nt][c0 + 1]));
            mx = fmaxf(mx, __shfl_xor_sync(0xffffffffu, mx, 1));
            mx = fmaxf(mx, __shfl_xor_sync(0xffffffffu, mx, 2));
            float mn = fmaxf(mrow[rr], mx);
            corr[rr] = __expf(mrow[rr] - mn);
            mrow[rr] = mn;
            float rs = 0.f;
#pragma unroll
            for (int nt = 0; nt < 8; nt++) {
                float e0 = __expf(s[mt][nt][c0] - mn);
                float e1 = __expf(s[mt][nt][c0 + 1] - mn);
                s[mt][nt][c0] = e0; s[mt][nt][c0 + 1] = e1;
                rs += e0 + e1;
            }
            rs += __shfl_xor_sync(0xffffffffu, rs, 1);
            rs += __shfl_xor_sync(0xffffffffu, rs, 2);
            lrow[rr] = lrow[rr] * corr[rr] + rs;
        }
#pragma unroll
        for (int mt = 0; mt < 2; mt++)
#pragma unroll
            for (int dn = 0; dn < 8; dn++) {
                o[mt][dn][0] *= corr[mt * 2];
                o[mt][dn][1] *= corr[mt * 2];
                o[mt][dn][2] *= corr[mt * 2 + 1];
                o[mt][dn][3] *= corr[mt * 2 + 1];
            }

        // ---- O += P @ V (1-pass)
#pragma unroll
        for (int kk = 0; kk < 4; kk++) {
            uint32_t vhf[4][4];
#pragma unroll
            for (int dp = 0; dp < 4; dp++) {
                uint32_t rv = (uint32_t)(kk * 16 * 144) + dp * 32 + laneA;
                ldm_x4_t(vhf[dp], s0 + AV + rv);
            }
#pragma unroll
            for (int mt = 0; mt < 2; mt++) {
                uint32_t ph[4];
                ph[0] = pack2h(s[mt][2 * kk][0],     s[mt][2 * kk][1]);
                ph[1] = pack2h(s[mt][2 * kk][2],     s[mt][2 * kk][3]);
                ph[2] = pack2h(s[mt][2 * kk + 1][0], s[mt][2 * kk + 1][1]);
                ph[3] = pack2h(s[mt][2 * kk + 1][2], s[mt][2 * kk + 1][3]);
#pragma unroll
                for (int dn = 0; dn < 8; dn++) {
                    uint32_t h0 = vhf[dn >> 1][(dn & 1) * 2];
                    uint32_t h1 = vhf[dn >> 1][(dn & 1) * 2 + 1];
                    mma16816h(o[mt][dn], ph, h0, h1);
                }
            }
        }
    }

    // ---- epilogue: normalize, write fp16 for the Wo GEMM
    float inv[4];
#pragma unroll
    for (int rr = 0; rr < 4; rr++) inv[rr] = 1.f / lrow[rr];
#pragma unroll
    for (int mt = 0; mt < 2; mt++) {
        size_t row0 = tok0 + wid * 32 + mt * 16 + (lane >> 2);
#pragma unroll
        for (int dn = 0; dn < 8; dn++) {
            int col = h * 64 + dn * 8 + (lane & 3) * 2;
            *(uint32_t*)(Og + row0 * D_MODEL + col) =
                pack2h(o[mt][dn][0] * inv[mt * 2], o[mt][dn][1] * inv[mt * 2]);
            *(uint32_t*)(Og + (row0 + 8) * D_MODEL + col) =
                pack2h(o[mt][dn][2] * inv[mt * 2 + 1], o[mt][dn][3] * inv[mt * 2 + 1]);
        }
    }
}

// ---------------------------------------------------------------------------
extern "C" void kernel_launch(void* const* d_in, const int* in_sizes, int n_in,
                              void* d_out, int out_size)
{
    const float* q  = (const float*)d_in[0];
    const float* k  = (const float*)d_in[1];
    const float* v  = (const float*)d_in[2];
    const float* Wq = (const float*)d_in[3];
    const float* bq = (const float*)d_in[4];
    const float* Wk = (const float*)d_in[5];
    const float* bk = (const float*)d_in[6];
    const float* Wv = (const float*)d_in[7];
    const float* bv = (const float*)d_in[8];
    const float* Wo = (const float*)d_in[9];
    const float* bo = (const float*)d_in[10];
    float* out = (float*)d_out;

    __half *qin, *kin, *vin;
    __half *Wqh, *Wql, *Wkh, *Wkl, *Wvh, *Wvl, *Woh, *Wol;
    __half *Qp, *Kph, *Kpl, *Vp, *Att;
    cudaGetSymbolAddress((void**)&qin, g_qin);
    cudaGetSymbolAddress((void**)&kin, g_kin);
    cudaGetSymbolAddress((void**)&vin, g_vin);
    cudaGetSymbolAddress((void**)&Wqh, g_Wqh); cudaGetSymbolAddress((void**)&Wql, g_Wql);
    cudaGetSymbolAddress((void**)&Wkh, g_Wkh); cudaGetSymbolAddress((void**)&Wkl, g_Wkl);
    cudaGetSymbolAddress((void**)&Wvh, g_Wvh); cudaGetSymbolAddress((void**)&Wvl, g_Wvl);
    cudaGetSymbolAddress((void**)&Woh, g_Woh); cudaGetSymbolAddress((void**)&Wol, g_Wol);
    cudaGetSymbolAddress((void**)&Qp,  g_Qp);
    cudaGetSymbolAddress((void**)&Kph, g_Kph); cudaGetSymbolAddress((void**)&Kpl, g_Kpl);
    cudaGetSymbolAddress((void**)&Vp,  g_Vp);
    cudaGetSymbolAddress((void**)&Att, g_Att);

    cudaFuncSetAttribute(gemm_f16,
                         cudaFuncAttributeMaxDynamicSharedMemorySize, GSM_B);
    cudaFuncSetAttribute(attn_mma,
                         cudaFuncAttributeMaxDynamicSharedMemorySize, A_SMEM);

    // producers: convert activations to fp16; split weights
    cvt_f16<<<dim3(512, 1, 3), 256>>>(q, qin, k, kin, v, vin, (int)(ACT_N / 4));
    wsplit_f16<<<dim3(256, 1, 4), 256>>>(Wq, Wqh, Wql, Wk, Wkh, Wkl,
                                         Wv, Wvh, Wvl, Wo, Woh, Wol,
                                         (int)(W_N / 4));

    // fused Q/K/V projections; epilogues emit attention-ready formats
    dim3 pgrid(D_MODEL / 128, NTOK / 128, 3);
    gemm_f16<<<pgrid, 256, GSM_B>>>(qin, Wqh, Wql, bq, Qp,  nullptr,
                                    kin, Wkh, Wkl, bk, Kph, Kpl,
                                    vin, Wvh, Wvl, bv, Vp,  nullptr,
                                    1);

    attn_mma<<<dim3(SEQ / 128, BATCH * NHEAD), 128, A_SMEM>>>(Qp, Kph, Kpl, Vp, Att);

    // output projection: fp32 out
    dim3 ogrid(D_MODEL / 128, NTOK / 128, 1);
    gemm_f16<<<ogrid, 256, GSM_B>>>(Att, Woh, Wol, bo, out, nullptr,
                                    Att, Woh, Wol, bo, out, nullptr,
                                    Att, Woh, Wol, bo, out, nullptr,
                                    0);
}

// round 12
// speedup vs baseline: 1.7358x; 1.1403x over previous
#include <cuda_runtime.h>
#include <cuda_fp16.h>
#include <cstdint>

#define D_MODEL 1024
#define NHEAD   16
#define HDIM    64
#define BATCH   4
#define SEQ     2048
#define NTOK    (BATCH*SEQ)

#define ACT_N ((size_t)NTOK * D_MODEL)
#define W_N   ((size_t)D_MODEL * D_MODEL)

// Scratch (allocation-free per harness rules) — all fp16
__device__ __half g_qin[ACT_N], g_kin[ACT_N], g_vin[ACT_N];
__device__ __half g_Wqh[W_N], g_Wql[W_N], g_Wkh[W_N], g_Wkl[W_N];
__device__ __half g_Wvh[W_N], g_Wvl[W_N], g_Woh[W_N], g_Wol[W_N];
__device__ __half g_Qp[ACT_N];                 // scaled by log2(e)/8
__device__ __half g_Kph[ACT_N], g_Kpl[ACT_N];  // split hi/lo
__device__ __half g_Vp[ACT_N];
__device__ __half g_Att[ACT_N];

// ---------------------------------------------------------------------------
// helpers
// ---------------------------------------------------------------------------
__device__ __forceinline__ uint32_t smem_u32(const void* p) {
    uint32_t a;
    asm("{ .reg .u64 t; cvta.to.shared.u64 t, %1; cvt.u32.u64 %0, t; }"
        : "=r"(a) : "l"(p));
    return a;
}
__device__ __forceinline__ void ldm_x4(uint32_t r[4], uint32_t addr) {
    asm volatile("ldmatrix.sync.aligned.m8n8.x4.shared.b16 {%0,%1,%2,%3}, [%4];"
                 : "=r"(r[0]), "=r"(r[1]), "=r"(r[2]), "=r"(r[3]) : "r"(addr));
}
__device__ __forceinline__ void ldm_x4_t(uint32_t r[4], uint32_t addr) {
    asm volatile("ldmatrix.sync.aligned.m8n8.x4.trans.shared.b16 {%0,%1,%2,%3}, [%4];"
                 : "=r"(r[0]), "=r"(r[1]), "=r"(r[2]), "=r"(r[3]) : "r"(addr));
}
__device__ __forceinline__ void mma16816h(float c[4], const uint32_t a[4],
                                          uint32_t b0, uint32_t b1) {
    asm volatile(
        "mma.sync.aligned.m16n8k16.row.col.f32.f16.f16.f32 "
        "{%0,%1,%2,%3}, {%4,%5,%6,%7}, {%8,%9}, {%0,%1,%2,%3};"
        : "+f"(c[0]), "+f"(c[1]), "+f"(c[2]), "+f"(c[3])
        : "r"(a[0]), "r"(a[1]), "r"(a[2]), "r"(a[3]), "r"(b0), "r"(b1));
}
__device__ __forceinline__ void split2h(float f0, float f1,
                                        uint32_t& hi, uint32_t& lo) {
    __half2 h = __floats2half2_rn(f0, f1);
    float2 hf = __half22float2(h);
    __half2 l = __floats2half2_rn(f0 - hf.x, f1 - hf.y);
    hi = *(uint32_t*)&h; lo = *(uint32_t*)&l;
}
__device__ __forceinline__ uint32_t pack2h(float f0, float f1) {
    __half2 h = __floats2half2_rn(f0, f1);
    return *(uint32_t*)&h;
}
__device__ __forceinline__ void cp16(uint32_t dst, const void* src) {
    asm volatile("cp.async.cg.shared.global [%0], [%1], 16;"
                 :: "r"(dst), "l"(src) : "memory");
}
__device__ __forceinline__ void cp_commit() {
    asm volatile("cp.async.commit_group;" ::: "memory");
}
#define CP_WAIT(n) asm volatile("cp.async.wait_group %0;" :: "n"(n) : "memory")

// ------------------------- producer conversion kernels ----------------------
__global__ void cvt_f16(const float* __restrict__ x0, __half* __restrict__ y0,
                        const float* __restrict__ x1, __half* __restrict__ y1,
                        const float* __restrict__ x2, __half* __restrict__ y2,
                        int n4)
{
    const float* x = (blockIdx.z == 0) ? x0 : (blockIdx.z == 1) ? x1 : x2;
    __half*      y = (blockIdx.z == 0) ? y0 : (blockIdx.z == 1) ? y1 : y2;
    int i = blockIdx.x * blockDim.x + threadIdx.x;
    int stride = gridDim.x * blockDim.x;
    for (; i < n4; i += stride) {
        float4 v = ((const float4*)x)[i];
        uint2 r;
        r.x = pack2h(v.x, v.y);
        r.y = pack2h(v.z, v.w);
        ((uint2*)y)[i] = r;
    }
}

__global__ void wsplit_f16(const float* __restrict__ x0, __half* __restrict__ h0, __half* __restrict__ l0,
                           const float* __restrict__ x1, __half* __restrict__ h1, __half* __restrict__ l1,
                           const float* __restrict__ x2, __half* __restrict__ h2, __half* __restrict__ l2,
                           const float* __restrict__ x3, __half* __restrict__ h3, __half* __restrict__ l3,
                           int n4)
{
    int z = blockIdx.z;
    const float* x = (z == 0) ? x0 : (z == 1) ? x1 : (z == 2) ? x2 : x3;
    __half*     yh = (z == 0) ? h0 : (z == 1) ? h1 : (z == 2) ? h2 : h3;
    __half*     yl = (z == 0) ? l0 : (z == 1) ? l1 : (z == 2) ? l2 : l3;
    int i = blockIdx.x * blockDim.x + threadIdx.x;
    int stride = gridDim.x * blockDim.x;
    for (; i < n4; i += stride) {
        float4 v = ((const float4*)x)[i];
        uint2 h, l;
        split2h(v.x, v.y, h.x, l.x);
        split2h(v.z, v.w, h.y, l.y);
        ((uint2*)yh)[i] = h;
        ((uint2*)yl)[i] = l;
    }
}

// ---------------------------------------------------------------------------
// GEMM: C[8192,1024] = A @ W^T + bias — fp16 2-pass, all-fp16 inputs (R11).
// Epilogue mode = base_mode + z:
//   0: fp32 out   1: fp16 scaled log2e/8 [Q]   2: fp16 split hi/lo [K]
//   3: fp16 [V]
// ---------------------------------------------------------------------------
#define GT_B    18432
#define GSTG_B  (3 * GT_B)
#define GSM_B   (2 * GSTG_B)

#define QSCALE  0.18033688f   // 0.125 * log2(e)

__global__ __launch_bounds__(256, 1)
void gemm_f16(const __half* __restrict__ A0, const __half* __restrict__ Wh0,
              const __half* __restrict__ Wl0, const float* __restrict__ b0_,
              void* O0a, void* O0b,
              const __half* __restrict__ A1, const __half* __restrict__ Wh1,
              const __half* __restrict__ Wl1, const float* __restrict__ b1_,
              void* O1a, void* O1b,
              const __half* __restrict__ A2, const __half* __restrict__ Wh2,
              const __half* __restrict__ Wl2, const float* __restrict__ b2_,
              void* O2a, void* O2b,
              int base_mode)
{
    extern __shared__ char sm[];
    const uint32_t s0 = smem_u32(sm);

    const int z = blockIdx.z;
    const __half* A    = (z == 0) ? A0  : (z == 1) ? A1  : A2;
    const __half* Wh   = (z == 0) ? Wh0 : (z == 1) ? Wh1 : Wh2;
    const __half* Wl   = (z == 0) ? Wl0 : (z == 1) ? Wl1 : Wl2;
    const float*  bias = (z == 0) ? b0_ : (z == 1) ? b1_ : b2_;
    void* Oa = (z == 0) ? O0a : (z == 1) ? O1a : O2a;
    void* Ob = (z == 0) ? O0b : (z == 1) ? O1b : O2b;
    const int mode = base_mode + z;

    const int tid  = threadIdx.x;
    const int lane = tid & 31;
    const int wid  = tid >> 5;
    const int bm = blockIdx.y * 128;
    const int bn = blockIdx.x * 128;
    const int wm = (wid >> 2) * 64;
    const int wn = (wid & 3) * 32;

    float acc[4][4][4];
#pragma unroll
    for (int i = 0; i < 4; i++)
#pragma unroll
        for (int j = 0; j < 4; j++)
#pragma unroll
            for (int q = 0; q < 4; q++) acc[i][j][q] = 0.f;

    const uint32_t offA = (uint32_t)(lane & 15) * 144 + (uint32_t)(lane >> 4) * 16;
    const uint32_t offB = (uint32_t)((lane & 7) + ((lane >> 4) & 1) * 8) * 144
                        + (uint32_t)((lane >> 3) & 1) * 16;

    uint4 aw[4], whw[4], wlw[4];
#pragma unroll
    for (int j = 0; j < 4; j++) {
        int c = tid + j * 256;
        int row = c >> 3, seg = c & 7;
        aw[j]  = *(const uint4*)(A  + (size_t)(bm + row) * D_MODEL + seg * 8);
        whw[j] = *(const uint4*)(Wh + (size_t)(bn + row) * D_MODEL + seg * 8);
        wlw[j] = *(const uint4*)(Wl + (size_t)(bn + row) * D_MODEL + seg * 8);
    }
    {
        char* stg = sm;
#pragma unroll
        for (int j = 0; j < 4; j++) {
            int c = tid + j * 256;
            int row = c >> 3, seg = c & 7;
            uint32_t ad = (uint32_t)(row * 144 + seg * 16);
            *(uint4*)(stg + 0 * GT_B + ad) = aw[j];
            *(uint4*)(stg + 1 * GT_B + ad) = whw[j];
            *(uint4*)(stg + 2 * GT_B + ad) = wlw[j];
        }
    }
    __syncthreads();

    for (int kt = 0; kt < 16; kt++) {
        if (kt < 15) {
            const int k0 = (kt + 1) * 64;
#pragma unroll
            for (int j = 0; j < 4; j++) {
                int c = tid + j * 256;
                int row = c >> 3, seg = c & 7;
                aw[j]  = *(const uint4*)(A  + (size_t)(bm + row) * D_MODEL + k0 + seg * 8);
                whw[j] = *(const uint4*)(Wh + (size_t)(bn + row) * D_MODEL + k0 + seg * 8);
                wlw[j] = *(const uint4*)(Wl + (size_t)(bn + row) * D_MODEL + k0 + seg * 8);
            }
        }

        const uint32_t sb  = s0 + (uint32_t)(kt & 1) * GSTG_B;
        const uint32_t sA  = sb;
        const uint32_t sWh = sb + 1 * GT_B;
        const uint32_t sWl = sb + 2 * GT_B;

#pragma unroll
        for (int ks = 0; ks < 4; ks++) {
            uint32_t ah[4][4], wh[2][4], wl[2][4];
            const uint32_t ka = (uint32_t)ks * 32;
#pragma unroll
            for (int mt = 0; mt < 4; mt++) {
                uint32_t ra = (uint32_t)((wm + mt * 16) * 144) + offA + ka;
                ldm_x4(ah[mt], sA + ra);
            }
#pragma unroll
            for (int p = 0; p < 2; p++) {
                uint32_t rb = (uint32_t)((wn + p * 16) * 144) + offB + ka;
                ldm_x4(wh[p], sWh + rb);
                ldm_x4(wl[p], sWl + rb);
            }
#pragma unroll
            for (int mt = 0; mt < 4; mt++)
#pragma unroll
                for (int nt = 0; nt < 4; nt++) {
                    uint32_t h0 = wh[nt >> 1][(nt & 1) * 2];
                    uint32_t h1 = wh[nt >> 1][(nt & 1) * 2 + 1];
                    uint32_t l0 = wl[nt >> 1][(nt & 1) * 2];
                    uint32_t l1 = wl[nt >> 1][(nt & 1) * 2 + 1];
                    mma16816h(acc[mt][nt], ah[mt], h0, h1);
                    mma16816h(acc[mt][nt], ah[mt], l0, l1);
                }
        }

        if (kt < 15) {
            char* stg = sm + ((kt + 1) & 1) * GSTG_B;
#pragma unroll
            for (int j = 0; j < 4; j++) {
                int c = tid + j * 256;
                int row = c >> 3, seg = c & 7;
                uint32_t ad = (uint32_t)(row * 144 + seg * 16);
                *(uint4*)(stg + 0 * GT_B + ad) = aw[j];
                *(uint4*)(stg + 1 * GT_B + ad) = whw[j];
                *(uint4*)(stg + 2 * GT_B + ad) = wlw[j];
            }
        }
        __syncthreads();
    }

#pragma unroll
    for (int mt = 0; mt < 4; mt++) {
        int row0 = bm + wm + mt * 16 + (lane >> 2);
#pragma unroll
        for (int nt = 0; nt < 4; nt++) {
            int col = bn + wn + nt * 8 + (lane & 3) * 2;
            float2 b2 = *(const float2*)&bias[col];
            float c0 = acc[mt][nt][0] + b2.x, c1 = acc[mt][nt][1] + b2.y;
            float c2 = acc[mt][nt][2] + b2.x, c3 = acc[mt][nt][3] + b2.y;
            size_t i0 = (size_t)row0 * D_MODEL + col;
            size_t i1 = (size_t)(row0 + 8) * D_MODEL + col;
            if (mode == 0) {
                *(float2*)((float*)Oa + i0) = make_float2(c0, c1);
                *(float2*)((float*)Oa + i1) = make_float2(c2, c3);
            } else if (mode == 1) {       // Q: fp16 scaled log2e/8
                *(uint32_t*)((__half*)Oa + i0) = pack2h(c0 * QSCALE, c1 * QSCALE);
                *(uint32_t*)((__half*)Oa + i1) = pack2h(c2 * QSCALE, c3 * QSCALE);
            } else if (mode == 2) {       // K: split hi/lo
                uint32_t h, l;
                split2h(c0, c1, h, l);
                *(uint32_t*)((__half*)Oa + i0) = h;
                *(uint32_t*)((__half*)Ob + i0) = l;
                split2h(c2, c3, h, l);
                *(uint32_t*)((__half*)Oa + i1) = h;
                *(uint32_t*)((__half*)Ob + i1) = l;
            } else {                       // V: plain fp16
                *(uint32_t*)((__half*)Oa + i0) = pack2h(c0, c1);
                *(uint32_t*)((__half*)Oa + i1) = pack2h(c2, c3);
            }
        }
    }
}

// ---------------------------------------------------------------------------
// Flash attention — R11 mainloop + cp.async 2-stage KV pipeline + exp2
// softmax (scores arrive in log2 domain via Q prescale).
// 128 thr, 4 warps x 32 q-rows, BN=64 KV tile.
// smem: Q[128][72]h, then 2 stages of (Kh|Kl|V)[64][72]h = 73.7 KB.
// ---------------------------------------------------------------------------
#define AQ    0
#define AKV0  18432
#define AT    9216                    // one 64x144B tile
#define AST   (3 * AT)                // Kh|Kl|V stage = 27648
#define A_SMEM (AKV0 + 2 * AST)       // 73728

__global__ __launch_bounds__(128)
void attn_mma(const __half* __restrict__ Qp, const __half* __restrict__ Kh_,
              const __half* __restrict__ Kl_, const __half* __restrict__ Vp,
              __half* __restrict__ Og)
{
    extern __shared__ char sm[];
    const uint32_t s0 = smem_u32(sm);

    const int tid  = threadIdx.x;
    const int lane = tid & 31;
    const int wid  = tid >> 5;
    const int qt = blockIdx.x;          // 16 q-tiles
    const int bh = blockIdx.y;          // 64 (b,h)
    const int b = bh >> 4, h = bh & 15;

    const size_t tok0 = (size_t)b * SEQ + qt * 128;
    const __half* Qb  = Qp  + tok0 * D_MODEL + h * 64;
    const __half* Khb = Kh_ + (size_t)b * SEQ * D_MODEL + h * 64;
    const __half* Klb = Kl_ + (size_t)b * SEQ * D_MODEL + h * 64;
    const __half* Vb  = Vp  + (size_t)b * SEQ * D_MODEL + h * 64;

    const uint32_t laneA = (uint32_t)(((lane >> 3) & 1) * 8 + (lane & 7)) * 144
                         + (uint32_t)(lane >> 4) * 16;
    const uint32_t laneB = (uint32_t)((lane >> 4) * 8 + (lane & 7)) * 144
                         + (uint32_t)((lane >> 3) & 1) * 16;
    const uint32_t wq = (uint32_t)wid * 32 * 144;

    // KV stage issue via cp.async: 12 x 16B per thread (3 tiles x 512 chunks)
    auto issue_kv = [&](int kt) {
        const uint32_t sb = s0 + AKV0 + (uint32_t)(kt & 1) * AST;
        const size_t rb = (size_t)kt * 64 * D_MODEL;
#pragma unroll
        for (int j = 0; j < 4; j++) {
            int c = tid + j * 128;
            int row = c >> 3, seg = c & 7;
            size_t go = rb + (size_t)row * D_MODEL + seg * 8;
            uint32_t ad = (uint32_t)(row * 144 + seg * 16);
            cp16(sb + 0 * AT + ad, Khb + go);
            cp16(sb + 1 * AT + ad, Klb + go);
            cp16(sb + 2 * AT + ad, Vb  + go);
        }
        cp_commit();
    };

    // Q tile: plain 16B copies
#pragma unroll
    for (int j = 0; j < 8; j++) {
        int c = tid + j * 128;
        int row = c >> 3, seg = c & 7;
        *(uint4*)(sm + AQ + row * 144 + seg * 16) =
            *(const uint4*)(Qb + (size_t)row * D_MODEL + seg * 8);
    }
    issue_kv(0);
    issue_kv(1);

    float o[2][8][4];
#pragma unroll
    for (int mt = 0; mt < 2; mt++)
#pragma unroll
        for (int dn = 0; dn < 8; dn++)
#pragma unroll
            for (int q = 0; q < 4; q++) o[mt][dn][q] = 0.f;
    float mrow[4] = {-1e30f, -1e30f, -1e30f, -1e30f};
    float lrow[4] = {0.f, 0.f, 0.f, 0.f};

    for (int kt = 0; kt < SEQ / 64; kt++) {
        CP_WAIT(1);            // stage kt landed
        __syncthreads();       // visible to all; everyone done with kt-1 smem

        const uint32_t kb = s0 + AKV0 + (uint32_t)(kt & 1) * AST;

        // ---- S = Q @ K^T (2-pass); scores in log2 domain
        float s[2][8][4];
#pragma unroll
        for (int mt = 0; mt < 2; mt++)
#pragma unroll
            for (int nt = 0; nt < 8; nt++)
#pragma unroll
                for (int q = 0; q < 4; q++) s[mt][nt][q] = 0.f;

#pragma unroll
        for (int k = 0; k < 4; k++) {
            uint32_t bhf[4][4], blf[4][4];
#pragma unroll
            for (int np = 0; np < 4; np++) {
                uint32_t rbb = (uint32_t)(np * 16 * 144) + k * 32 + laneB;
                ldm_x4(bhf[np], kb + 0 * AT + rbb);
                ldm_x4(blf[np], kb + 1 * AT + rbb);
            }
#pragma unroll
            for (int mt = 0; mt < 2; mt++) {
                uint32_t ah[4];
                uint32_t ra = wq + (uint32_t)(mt * 16 * 144) + k * 32 + laneA;
                ldm_x4(ah, s0 + AQ + ra);
#pragma unroll
                for (int nt = 0; nt < 8; nt++) {
                    uint32_t h0 = bhf[nt >> 1][(nt & 1) * 2];
                    uint32_t h1 = bhf[nt >> 1][(nt & 1) * 2 + 1];
                    uint32_t l0 = blf[nt >> 1][(nt & 1) * 2];
                    uint32_t l1 = blf[nt >> 1][(nt & 1) * 2 + 1];
                    mma16816h(s[mt][nt], ah, h0, h1);
                    mma16816h(s[mt][nt], ah, l0, l1);
                }
            }
        }

        // ---- online softmax (exp2 domain)
        float corr[4];
#pragma unroll
        for (int rr = 0; rr < 4; rr++) {
            int mt = rr >> 1, c0 = (rr & 1) * 2;
            float mx = -1e30f;
#pragma unroll
            for (int nt = 0; nt < 8; nt++)
                mx = fmaxf(mx, fmaxf(s[mt][nt][c0], s[mt][nt][c0 + 1]));
            mx = fmaxf(mx, __shfl_xor_sync(0xffffffffu, mx, 1));
            mx = fmaxf(mx, __shfl_xor_sync(0xffffffffu, mx, 2));
            float mn = fmaxf(mrow[rr], mx);
            corr[rr] = exp2f(mrow[rr] - mn);
            mrow[rr] = mn;
            float rs = 0.f;
#pragma unroll
            for (int nt = 0; nt < 8; nt++) {
                float e0 = exp2f(s[mt][nt][c0] - mn);
                float e1 = exp2f(s[mt][nt][c0 + 1] - mn);
                s[mt][nt][c0] = e0; s[mt][nt][c0 + 1] = e1;
                rs += e0 + e1;
            }
            rs += __shfl_xor_sync(0xffffffffu, rs, 1);
            rs += __shfl_xor_sync(0xffffffffu, rs, 2);
            lrow[rr] = lrow[rr] * corr[rr] + rs;
        }
#pragma unroll
        for (int mt = 0; mt < 2; mt++)
#pragma unroll
            for (int dn = 0; dn < 8; dn++) {
                o[mt][dn][0] *= corr[mt * 2];
                o[mt][dn][1] *= corr[mt * 2];
                o[mt][dn][2] *= corr[mt * 2 + 1];
                o[mt][dn][3] *= corr[mt * 2 + 1];
            }

        // ---- O += P @ V (1-pass)
#pragma unroll
        for (int kk = 0; kk < 4; kk++) {
            uint32_t vhf[4][4];
#pragma unroll
            for (int dp = 0; dp < 4; dp++) {
                uint32_t rv = (uint32_t)(kk * 16 * 144) + dp * 32 + laneA;
                ldm_x4_t(vhf[dp], kb + 2 * AT + rv);
            }
#pragma unroll
            for (int mt = 0; mt < 2; mt++) {
                uint32_t ph[4];
                ph[0] = pack2h(s[mt][2 * kk][0],     s[mt][2 * kk][1]);
                ph[1] = pack2h(s[mt][2 * kk][2],     s[mt][2 * kk][3]);
                ph[2] = pack2h(s[mt][2 * kk + 1][0], s[mt][2 * kk + 1][1]);
                ph[3] = pack2h(s[mt][2 * kk + 1][2], s[mt][2 * kk + 1][3]);
#pragma unroll
                for (int dn = 0; dn < 8; dn++) {
                    uint32_t h0 = vhf[dn >> 1][(dn & 1) * 2];
                    uint32_t h1 = vhf[dn >> 1][(dn & 1) * 2 + 1];
                    mma16816h(o[mt][dn], ph, h0, h1);
                }
            }
        }

        __syncthreads();                       // all reads of buffer kt&1 done
        if (kt + 2 < SEQ / 64) issue_kv(kt + 2);
    }

    // ---- epilogue: normalize, write fp16 for the Wo GEMM
    float inv[4];
#pragma unroll
    for (int rr = 0; rr < 4; rr++) inv[rr] = 1.f / lrow[rr];
#pragma unroll
    for (int mt = 0; mt < 2; mt++) {
        size_t row0 = tok0 + wid * 32 + mt * 16 + (lane >> 2);
#pragma unroll
        for (int dn = 0; dn < 8; dn++) {
            int col = h * 64 + dn * 8 + (lane & 3) * 2;
            *(uint32_t*)(Og + row0 * D_MODEL + col) =
                pack2h(o[mt][dn][0] * inv[mt * 2], o[mt][dn][1] * inv[mt * 2]);
            *(uint32_t*)(Og + (row0 + 8) * D_MODEL + col) =
                pack2h(o[mt][dn][2] * inv[mt * 2 + 1], o[mt][dn][3] * inv[mt * 2 + 1]);
        }
    }
}

// ---------------------------------------------------------------------------
extern "C" void kernel_launch(void* const* d_in, const int* in_sizes, int n_in,
                              void* d_out, int out_size)
{
    const float* q  = (const float*)d_in[0];
    const float* k  = (const float*)d_in[1];
    const float* v  = (const float*)d_in[2];
    const float* Wq = (const float*)d_in[3];
    const float* bq = (const float*)d_in[4];
    const float* Wk = (const float*)d_in[5];
    const float* bk = (const float*)d_in[6];
    const float* Wv = (const float*)d_in[7];
    const float* bv = (const float*)d_in[8];
    const float* Wo = (const float*)d_in[9];
    const float* bo = (const float*)d_in[10];
    float* out = (float*)d_out;

    __half *qin, *kin, *vin;
    __half *Wqh, *Wql, *Wkh, *Wkl, *Wvh, *Wvl, *Woh, *Wol;
    __half *Qp, *Kph, *Kpl, *Vp, *Att;
    cudaGetSymbolAddress((void**)&qin, g_qin);
    cudaGetSymbolAddress((void**)&kin, g_kin);
    cudaGetSymbolAddress((void**)&vin, g_vin);
    cudaGetSymbolAddress((void**)&Wqh, g_Wqh); cudaGetSymbolAddress((void**)&Wql, g_Wql);
    cudaGetSymbolAddress((void**)&Wkh, g_Wkh); cudaGetSymbolAddress((void**)&Wkl, g_Wkl);
    cudaGetSymbolAddress((void**)&Wvh, g_Wvh); cudaGetSymbolAddress((void**)&Wvl, g_Wvl);
    cudaGetSymbolAddress((void**)&Woh, g_Woh); cudaGetSymbolAddress((void**)&Wol, g_Wol);
    cudaGetSymbolAddress((void**)&Qp,  g_Qp);
    cudaGetSymbolAddress((void**)&Kph, g_Kph); cudaGetSymbolAddress((void**)&Kpl, g_Kpl);
    cudaGetSymbolAddress((void**)&Vp,  g_Vp);
    cudaGetSymbolAddress((void**)&Att, g_Att);

    cudaFuncSetAttribute(gemm_f16,
                         cudaFuncAttributeMaxDynamicSharedMemorySize, GSM_B);
    cudaFuncSetAttribute(attn_mma,
                         cudaFuncAttributeMaxDynamicSharedMemorySize, A_SMEM);

    cvt_f16<<<dim3(512, 1, 3), 256>>>(q, qin, k, kin, v, vin, (int)(ACT_N / 4));
    wsplit_f16<<<dim3(256, 1, 4), 256>>>(Wq, Wqh, Wql, Wk, Wkh, Wkl,
                                         Wv, Wvh, Wvl, Wo, Woh, Wol,
                                         (int)(W_N / 4));

    dim3 pgrid(D_MODEL / 128, NTOK / 128, 3);
    gemm_f16<<<pgrid, 256, GSM_B>>>(qin, Wqh, Wql, bq, Qp,  nullptr,
                                    kin, Wkh, Wkl, bk, Kph, Kpl,
                                    vin, Wvh, Wvl, bv, Vp,  nullptr,
                                    1);

    attn_mma<<<dim3(SEQ / 128, BATCH * NHEAD), 128, A_SMEM>>>(Qp, Kph, Kpl, Vp, Att);

    dim3 ogrid(D_MODEL / 128, NTOK / 128, 1);
    gemm_f16<<<ogrid, 256, GSM_B>>>(Att, Woh, Wol, bo, out, nullptr,
                                    Att, Woh, Wol, bo, out, nullptr,
                                    Att, Woh, Wol, bo, out, nullptr,
                                    0);
}